// round 4
// baseline (speedup 1.0000x reference)
#include <cuda_runtime.h>
#include <cstddef>

#define EPSRMS 1.1920929e-07f

// ---------------- persistent device scratch ----------------
__device__ float g_h0[16777216];
__device__ float g_h1[16777216];
__device__ float g_ff[16384*2816];
__device__ float g_WTfg[256*1024];
__device__ float g_WTgu[256*1024];
__device__ float g_ATfg[32*1024];
__device__ float g_ATgu[32*1024];
__device__ float g_BitT[128*1024];
__device__ float g_WTffg[128*2816];
__device__ float g_WTfff[128*2816];
__device__ float g_ATffg[32*2816];
__device__ float g_ATfff[32*2816];
__device__ float g_BfT[64*1024];
__device__ float g_WTffp[352*1024];
__device__ float g_ATffp[32*1024];

__device__ __forceinline__ void fma4(float4& a, float4 w, float s){
    a.x = fmaf(w.x, s, a.x); a.y = fmaf(w.y, s, a.y);
    a.z = fmaf(w.z, s, a.z); a.w = fmaf(w.w, s, a.w);
}
__device__ __forceinline__ float sigm(float x){ return 1.0f/(1.0f+__expf(-x)); }

// ---------------- prep kernels ----------------
// out[N][M] = in[M][N]^T
__global__ void tr_k(const float* __restrict__ in, float* __restrict__ out, int M, int N){
    __shared__ float t[32][33];
    int x = blockIdx.x*32 + threadIdx.x;
    for (int j = threadIdx.y; j < 32; j += 8){
        int y = blockIdx.y*32 + j;
        if (y < M && x < N) t[j][threadIdx.x] = in[(size_t)y*N + x];
    }
    __syncthreads();
    int xo = blockIdx.y*32 + threadIdx.x;
    for (int j = threadIdx.y; j < 32; j += 8){
        int yo = blockIdx.x*32 + j;
        if (yo < N && xo < M) out[(size_t)yo*M + xo] = t[threadIdx.x][j];
    }
}

// BitT[c][k], c<128, k<1024: c in [0,32): fg_B[c][k]; [32,64): fg_B[c-32][1024+k];
// [64,96): gu_B[c-64][k]; [96,128): gu_B[c-96][1024+k]
__global__ void bitT_k(const float* __restrict__ fgB, const float* __restrict__ guB){
    int idx = blockIdx.x*256 + threadIdx.x;
    if (idx >= 128*1024) return;
    int c = idx >> 10, k = idx & 1023;
    const float* B = (c & 64) ? guB : fgB;
    g_BitT[idx] = B[(c & 31)*2048 + ((c >> 5) & 1)*1024 + k];
}

// BfT[c][k], c<64: c<32 -> ffg_B[c][k]; else fff_B[c-32][k]
__global__ void bfT_k(const float* __restrict__ gB, const float* __restrict__ fB){
    int idx = blockIdx.x*256 + threadIdx.x;
    if (idx >= 64*1024) return;
    int c = idx >> 10, k = idx & 1023;
    g_BfT[idx] = (c < 32) ? gB[c*1024 + k] : fB[(c-32)*1024 + k];
}

// ---------------- iteration kernel ----------------
// Block: 16 tokens of one batch. smem z rows 0..16 (row 0 = halo token s0-1).
__global__ __launch_bounds__(256)
void iter_k(const float* __restrict__ hin, float* __restrict__ hout){
    extern __shared__ float sm[];
    float* z   = sm;               // 17*1024
    float* q2  = z  + 17*1024;     // 2*17*128 (half-split lowrank partials)
    float* ps  = q2 + 2*17*128;    // 16*64

    int tid = threadIdx.x, warp = tid >> 5, lane = tid & 31;
    int s0 = blockIdx.x * 16;
    const float* hb  = hin  + (size_t)blockIdx.y*2048*1024;
    float*       hob = hout + (size_t)blockIdx.y*2048*1024;

    // phase A: rmsnorm rows 0..16 (row r = token s0-1+r)
    for (int r = warp; r < 17; r += 8){
        int s = s0 - 1 + r;
        float* zr = z + r*1024;
        if (s < 0){
            for (int j = lane; j < 256; j += 32)
                ((float4*)zr)[j] = make_float4(0.f,0.f,0.f,0.f);
        } else {
            const float4* hr = (const float4*)(hb + (size_t)s*1024);
            float4 v[8]; float ss = 0.f;
            #pragma unroll
            for (int j = 0; j < 8; j++){
                v[j] = hr[lane + 32*j];
                ss += v[j].x*v[j].x + v[j].y*v[j].y + v[j].z*v[j].z + v[j].w*v[j].w;
            }
            #pragma unroll
            for (int o = 16; o; o >>= 1) ss += __shfl_xor_sync(0xffffffffu, ss, o);
            float sc = rsqrtf(ss*(1.f/1024.f) + EPSRMS);
            #pragma unroll
            for (int j = 0; j < 8; j++){
                float4 w = v[j];
                w.x *= sc; w.y *= sc; w.z *= sc; w.w *= sc;
                ((float4*)zr)[lane + 32*j] = w;
            }
        }
    }
    __syncthreads();

    // phase B: lowrank products. thread: col c = tid&127, k-half = tid>>7.
    // q2[half][r][c] = sum_{k in half} z[r][k] * BitT[c][k]
    {
        int c = tid & 127, half = tid >> 7;
        float acc[17];
        #pragma unroll
        for (int r = 0; r < 17; r++) acc[r] = 0.f;
        const float4* bt = (const float4*)(g_BitT + (size_t)c*1024 + half*512);
        for (int k4 = 0; k4 < 128; k4++){
            float4 b = bt[k4];
            #pragma unroll
            for (int r = 0; r < 17; r++){
                float4 zv = ((const float4*)(z + r*1024 + half*512))[k4];
                acc[r] = fmaf(b.x, zv.x, fmaf(b.y, zv.y, fmaf(b.z, zv.z, fmaf(b.w, zv.w, acc[r]))));
            }
        }
        #pragma unroll
        for (int r = 0; r < 17; r++) q2[(half*17 + r)*128 + c] = acc[r];
    }
    __syncthreads();

    // combine: ps[t][m*32+r] = q(t+1, m*64+r) + q(t, m*64+32+r), q = sum of halves
    for (int idx = tid; idx < 16*64; idx += 256){
        int t = idx >> 6, c = idx & 63, m = c >> 5, r = c & 31;
        int i1 = (t+1)*128 + m*64 + r;
        int i2 = t*128 + m*64 + 32 + r;
        ps[idx] = (q2[i1] + q2[17*128 + i1]) + (q2[i2] + q2[17*128 + i2]);
    }
    __syncthreads();

    // phase C: blockdiag + lowrank, gate*update, residual. warp = output block.
    {
        int n = warp;
        int zrow0 = (n < 4) ? 1 : 0;            // blocks 4..7 read shifted (z row t)
        int cb = (n & 3)*256;
        const float4* WG = (const float4*)g_WTfg;   // [256][256 f4]
        const float4* WU = (const float4*)g_WTgu;
        const float4* AG = (const float4*)g_ATfg;   // [32][256 f4]
        const float4* AU = (const float4*)g_ATgu;
        for (int tg = 0; tg < 2; tg++){
            float4 ag[8], au[8];
            #pragma unroll
            for (int t = 0; t < 8; t++){
                ag[t] = make_float4(0.f,0.f,0.f,0.f);
                au[t] = make_float4(0.f,0.f,0.f,0.f);
            }
            const float* zb = z + (zrow0 + tg*8)*1024 + cb;
            for (int i = 0; i < 256; i++){
                float4 wg = WG[i*256 + tid];
                float4 wu = WU[i*256 + tid];
                #pragma unroll
                for (int t = 0; t < 8; t++){
                    float s = zb[t*1024 + i];
                    fma4(ag[t], wg, s); fma4(au[t], wu, s);
                }
            }
            #pragma unroll 4
            for (int r = 0; r < 32; r++){
                float4 a1 = AG[r*256 + tid];
                float4 a2 = AU[r*256 + tid];
                #pragma unroll
                for (int t = 0; t < 8; t++){
                    fma4(ag[t], a1, ps[(tg*8 + t)*64 + r]);
                    fma4(au[t], a2, ps[(tg*8 + t)*64 + 32 + r]);
                }
            }
            #pragma unroll
            for (int t = 0; t < 8; t++){
                int s = s0 + tg*8 + t;
                float4 hv = ((const float4*)(hb + (size_t)s*1024))[tid];
                float4 g = ag[t], u = au[t], o;
                o.x = fmaf(sigm(g.x), u.x, hv.x);
                o.y = fmaf(sigm(g.y), u.y, hv.y);
                o.z = fmaf(sigm(g.z), u.z, hv.z);
                o.w = fmaf(sigm(g.w), u.w, hv.w);
                ((float4*)(hob + (size_t)s*1024))[tid] = o;
            }
        }
    }
}

// ---------------- final part 1: rmsnorm + ffg/fff + silu*mul -> g_ff ----------------
__global__ __launch_bounds__(256)
void final1_k(const float* __restrict__ hin){
    extern __shared__ float sm[];
    float* z   = sm;             // 8*1024
    float* q2f = z + 8*1024;     // 4*8*64
    float* q   = q2f + 2048;     // 8*64
    int tid = threadIdx.x, warp = tid >> 5, lane = tid & 31;
    size_t tok0 = (size_t)blockIdx.x*8;
    const float* hb = hin + tok0*1024;

    // A: rmsnorm, warp per row
    {
        const float4* hr = (const float4*)(hb + (size_t)warp*1024);
        float4 v[8]; float ss = 0.f;
        #pragma unroll
        for (int j = 0; j < 8; j++){
            v[j] = hr[lane + 32*j];
            ss += v[j].x*v[j].x + v[j].y*v[j].y + v[j].z*v[j].z + v[j].w*v[j].w;
        }
        #pragma unroll
        for (int o = 16; o; o >>= 1) ss += __shfl_xor_sync(0xffffffffu, ss, o);
        float sc = rsqrtf(ss*(1.f/1024.f) + EPSRMS);
        float4* zr = (float4*)(z + warp*1024);
        #pragma unroll
        for (int j = 0; j < 8; j++){
            float4 w = v[j];
            w.x *= sc; w.y *= sc; w.z *= sc; w.w *= sc;
            zr[lane + 32*j] = w;
        }
    }
    __syncthreads();

    // B: lowrank q[8][64] via k-quarter split
    {
        int c = tid & 63, qtr = tid >> 6;
        float acc[8];
        #pragma unroll
        for (int t = 0; t < 8; t++) acc[t] = 0.f;
        const float4* bt = (const float4*)(g_BfT + (size_t)c*1024 + qtr*256);
        for (int k4 = 0; k4 < 64; k4++){
            float4 b = bt[k4];
            #pragma unroll
            for (int t = 0; t < 8; t++){
                float4 zv = ((const float4*)(z + t*1024 + qtr*256))[k4];
                acc[t] = fmaf(b.x, zv.x, fmaf(b.y, zv.y, fmaf(b.z, zv.z, fmaf(b.w, zv.w, acc[t]))));
            }
        }
        #pragma unroll
        for (int t = 0; t < 8; t++) q2f[qtr*512 + t*64 + c] = acc[t];
    }
    __syncthreads();
    for (int idx = tid; idx < 512; idx += 256)
        q[idx] = q2f[idx] + q2f[512 + idx] + q2f[1024 + idx] + q2f[1536 + idx];
    __syncthreads();

    // C: ff = silu(ffg)*fff
    const float4* WG = (const float4*)g_WTffg;   // [128][704 f4]
    const float4* WF = (const float4*)g_WTfff;
    const float4* AG = (const float4*)g_ATffg;   // [32][704 f4]
    const float4* AF = (const float4*)g_ATfff;
    for (int fc = tid; fc < 704; fc += 256){
        int n = fc / 88;                         // 88 f4 per 352-wide out block
        const float* zb = z + n*128;
        float4 ag[8], af[8];
        #pragma unroll
        for (int t = 0; t < 8; t++){
            ag[t] = make_float4(0.f,0.f,0.f,0.f);
            af[t] = make_float4(0.f,0.f,0.f,0.f);
        }
        for (int i = 0; i < 128; i++){
            float4 wg = WG[(size_t)i*704 + fc];
            float4 wf = WF[(size_t)i*704 + fc];
            #pragma unroll
            for (int t = 0; t < 8; t++){
                float s = zb[t*1024 + i];
                fma4(ag[t], wg, s); fma4(af[t], wf, s);
            }
        }
        #pragma unroll 4
        for (int r = 0; r < 32; r++){
            float4 a1 = AG[(size_t)r*704 + fc];
            float4 a2 = AF[(size_t)r*704 + fc];
            #pragma unroll
            for (int t = 0; t < 8; t++){
                fma4(ag[t], a1, q[t*64 + r]);
                fma4(af[t], a2, q[t*64 + 32 + r]);
            }
        }
        #pragma unroll
        for (int t = 0; t < 8; t++){
            float4 g = ag[t], f = af[t], o;
            o.x = g.x*sigm(g.x)*f.x;
            o.y = g.y*sigm(g.y)*f.y;
            o.z = g.z*sigm(g.z)*f.z;
            o.w = g.w*sigm(g.w)*f.w;
            ((float4*)(g_ff + (tok0 + t)*2816))[fc] = o;
        }
    }
}

// ---------------- final part 2: ffp lslinear + residual -> out ----------------
__global__ __launch_bounds__(256)
void final2_k(const float* __restrict__ hin, float* __restrict__ out,
              const float* __restrict__ ffpB){
    extern __shared__ float sm[];
    float* ffs = sm;               // 8*2816
    float* pp2 = ffs + 8*2816;     // 8*8*32
    float* pp  = pp2 + 2048;       // 8*32
    int tid = threadIdx.x, warp = tid >> 5, lane = tid & 31;
    size_t tok0 = (size_t)blockIdx.x*8;

    // load ff tile
    {
        const float4* src = (const float4*)(g_ff + tok0*2816);
        float4* dst = (float4*)ffs;
        for (int i = tid; i < 8*704; i += 256) dst[i] = src[i];
    }
    __syncthreads();

    // D: pp[t][r] = ff[t] . ffp_B[r], k split in 8 chunks of 352
    {
        int r = lane, e = warp;
        float acc[8];
        #pragma unroll
        for (int t = 0; t < 8; t++) acc[t] = 0.f;
        const float4* bp = (const float4*)(ffpB + (size_t)r*2816 + e*352);
        for (int k4 = 0; k4 < 88; k4++){
            float4 b = bp[k4];
            #pragma unroll
            for (int t = 0; t < 8; t++){
                float4 fv = ((const float4*)(ffs + t*2816 + e*352))[k4];
                acc[t] = fmaf(b.x, fv.x, fmaf(b.y, fv.y, fmaf(b.z, fv.z, fmaf(b.w, fv.w, acc[t]))));
            }
        }
        #pragma unroll
        for (int t = 0; t < 8; t++) pp2[(e*8 + t)*32 + r] = acc[t];
    }
    __syncthreads();
    {
        int t = tid >> 5, r = tid & 31;
        float s = 0.f;
        #pragma unroll
        for (int e = 0; e < 8; e++) s += pp2[(e*8 + t)*32 + r];
        pp[t*32 + r] = s;
    }
    __syncthreads();

    // E: out = h + blockdiag(ffp_W).ff + ffp_A.pp, warp = output block
    const float4* WP = (const float4*)g_WTffp;   // [352][256 f4]
    const float4* AP = (const float4*)g_ATffp;   // [32][256 f4]
    const float* fb = ffs + warp*352;
    float4 a[8];
    #pragma unroll
    for (int t = 0; t < 8; t++) a[t] = make_float4(0.f,0.f,0.f,0.f);
    for (int i = 0; i < 352; i++){
        float4 w = WP[i*256 + tid];
        #pragma unroll
        for (int t = 0; t < 8; t++) fma4(a[t], w, fb[t*2816 + i]);
    }
    #pragma unroll 4
    for (int r = 0; r < 32; r++){
        float4 w = AP[r*256 + tid];
        #pragma unroll
        for (int t = 0; t < 8; t++) fma4(a[t], w, pp[t*32 + r]);
    }
    const float* hb = hin + tok0*1024;
    #pragma unroll
    for (int t = 0; t < 8; t++){
        float4 hv = ((const float4*)(hb + (size_t)t*1024))[tid];
        float4 o;
        o.x = a[t].x + hv.x; o.y = a[t].y + hv.y;
        o.z = a[t].z + hv.z; o.w = a[t].w + hv.w;
        ((float4*)(out + (tok0 + t)*1024))[tid] = o;
    }
}

// ---------------- launcher ----------------
template <typename T>
static float* symaddr(const T& s){
    void* p = nullptr;
    cudaGetSymbolAddress(&p, s);
    return (float*)p;
}

extern "C" void kernel_launch(void* const* d_in, const int* in_sizes, int n_in,
                              void* d_out, int out_size) {
    const float* x     = (const float*)d_in[0];
    const float* fg_W  = (const float*)d_in[1];
    const float* fg_A  = (const float*)d_in[2];
    const float* fg_B  = (const float*)d_in[3];
    const float* gu_W  = (const float*)d_in[4];
    const float* gu_A  = (const float*)d_in[5];
    const float* gu_B  = (const float*)d_in[6];
    const float* ffg_W = (const float*)d_in[7];
    const float* ffg_A = (const float*)d_in[8];
    const float* ffg_B = (const float*)d_in[9];
    const float* fff_W = (const float*)d_in[10];
    const float* fff_A = (const float*)d_in[11];
    const float* fff_B = (const float*)d_in[12];
    const float* ffp_W = (const float*)d_in[13];
    const float* ffp_A = (const float*)d_in[14];
    const float* ffp_B = (const float*)d_in[15];
    float* out = (float*)d_out;

    float* h0    = symaddr(g_h0);
    float* h1    = symaddr(g_h1);
    float* WTfg  = symaddr(g_WTfg);
    float* WTgu  = symaddr(g_WTgu);
    float* ATfg  = symaddr(g_ATfg);
    float* ATgu  = symaddr(g_ATgu);
    float* WTffg = symaddr(g_WTffg);
    float* WTfff = symaddr(g_WTfff);
    float* ATffg = symaddr(g_ATffg);
    float* ATfff = symaddr(g_ATfff);
    float* WTffp = symaddr(g_WTffp);
    float* ATffp = symaddr(g_ATffp);

    cudaFuncSetAttribute(iter_k,   cudaFuncAttributeMaxDynamicSharedMemorySize, 91136);
    cudaFuncSetAttribute(final2_k, cudaFuncAttributeMaxDynamicSharedMemorySize, 99328);

    dim3 tb(32, 8);
    tr_k<<<dim3(8, 32),  tb>>>(fg_W,  WTfg,  1024, 256);
    tr_k<<<dim3(8, 32),  tb>>>(gu_W,  WTgu,  1024, 256);
    tr_k<<<dim3(1, 32),  tb>>>(fg_A,  ATfg,  1024, 32);
    tr_k<<<dim3(1, 32),  tb>>>(gu_A,  ATgu,  1024, 32);
    tr_k<<<dim3(4, 88),  tb>>>(ffg_W, WTffg, 2816, 128);
    tr_k<<<dim3(4, 88),  tb>>>(fff_W, WTfff, 2816, 128);
    tr_k<<<dim3(1, 88),  tb>>>(ffg_A, ATffg, 2816, 32);
    tr_k<<<dim3(1, 88),  tb>>>(fff_A, ATfff, 2816, 32);
    tr_k<<<dim3(11, 32), tb>>>(ffp_W, WTffp, 1024, 352);
    tr_k<<<dim3(1, 32),  tb>>>(ffp_A, ATffp, 1024, 32);
    bitT_k<<<512, 256>>>(fg_B, gu_B);
    bfT_k<<<256, 256>>>(ffg_B, fff_B);

    dim3 ig(128, 8);
    iter_k<<<ig, 256, 91136>>>(x,  h0);
    iter_k<<<ig, 256, 91136>>>(h0, h1);
    iter_k<<<ig, 256, 91136>>>(h1, h0);
    iter_k<<<ig, 256, 91136>>>(h0, h1);

    final1_k<<<2048, 256, 43008>>>(h1);
    final2_k<<<2048, 256, 99328>>>(h1, out, ffp_B);
}

// round 6
// speedup vs baseline: 1.7267x; 1.7267x over previous
#include <cuda_runtime.h>
#include <cstdint>
#include <cstddef>

#define EPSRMS 1.1920929e-07f

// ---------------- persistent device scratch ----------------
__device__ float g_z  [16777216];         // rmsnorm output
__device__ float g_h0 [16777216];
__device__ float g_h1 [16777216];
__device__ float g_P  [16384*64];         // low-rank projections
__device__ float g_Pp [16384*32];         // low-rank projection for ffp
__device__ float g_ffg[16384*2816];       // raw ffg result
__device__ float g_ff [16384*2816];       // silu(ffg)*fff

// ---------------- helpers ----------------
__device__ __forceinline__ float sigm(float x){ return 1.0f/(1.0f+__expf(-x)); }

__device__ __forceinline__ float tf32r(float x){
    uint32_t u;
    asm("cvt.rna.tf32.f32 %0, %1;" : "=r"(u) : "f"(x));
    return __uint_as_float(u);
}

__device__ __forceinline__ void mma8(float4& d, uint4 a, uint2 b){
    asm volatile(
        "mma.sync.aligned.m16n8k8.row.col.f32.tf32.tf32.f32 "
        "{%0,%1,%2,%3},{%4,%5,%6,%7},{%8,%9},{%0,%1,%2,%3};"
        : "+f"(d.x), "+f"(d.y), "+f"(d.z), "+f"(d.w)
        : "r"(a.x), "r"(a.y), "r"(a.z), "r"(a.w), "r"(b.x), "r"(b.y));
}

// ---------------- fragment-permuted slab staging ----------------
// A slab: 128 rows x 32 cols -> Ap[kc][mt][lane][4] (float4 per (kc,mt,lane))
// element (r, c): kc=c>>3, mt=r>>4, lane=(r&7)*4+(c&3), j=((r>>3)&1)+2*((c>>2)&1)
__device__ __forceinline__ void fillA(float* Ap, const float* src, size_t ld, int tid){
    for (int i = tid; i < 1024; i += 256){
        int r = i >> 3, c4 = i & 7;
        float4 v = *(const float4*)(src + (size_t)r*ld + (c4<<2));
        const float* vp = &v.x;
        int mt = r >> 4, rr = r & 15;
        int lo = (rr >> 3) & 1, lb = (rr & 7) << 2;
        #pragma unroll
        for (int e = 0; e < 4; e++){
            int c = (c4<<2) + e;
            int ln = lb + (c & 3);
            int j  = lo + (((c >> 2) & 1) << 1);
            Ap[((((c >> 3) << 3) + mt)*32 + ln)*4 + j] = tf32r(vp[e]);
        }
    }
}

// A slab from token rows with causal shift (token = seq0 + r - shift; zero if < 0)
__device__ __forceinline__ void fillA_tok(float* Ap, const float* zb,
                                          int seq0, int shift, int colbase, int tid){
    for (int i = tid; i < 1024; i += 256){
        int r = i >> 3, c4 = i & 7;
        int s = seq0 + r - shift;
        float4 v = make_float4(0.f,0.f,0.f,0.f);
        if (s >= 0) v = *(const float4*)(zb + (size_t)s*1024 + colbase + (c4<<2));
        const float* vp = &v.x;
        int mt = r >> 4, rr = r & 15;
        int lo = (rr >> 3) & 1, lb = (rr & 7) << 2;
        #pragma unroll
        for (int e = 0; e < 4; e++){
            int c = (c4<<2) + e;
            int ln = lb + (c & 3);
            int j  = lo + (((c >> 2) & 1) << 1);
            Ap[((((c >> 3) << 3) + mt)*32 + ln)*4 + j] = tf32r(vp[e]);
        }
    }
}

// B slab: NR rows x 32 cols -> Bp[kc][nt][lane][2]
// element (n, c): kc=c>>3, nt=n>>3, lane=(n&7)*4+(c&3), j=(c>>2)&1
__device__ __forceinline__ void fillB(float* Bp, const float* src, size_t ld, int NR, int tid){
    int NT8 = NR >> 3;
    for (int i = tid; i < (NR << 3); i += 256){
        int n = i >> 3, c4 = i & 7;
        float4 v = *(const float4*)(src + (size_t)n*ld + (c4<<2));
        const float* vp = &v.x;
        int nt = n >> 3, lb = (n & 7) << 2;
        #pragma unroll
        for (int e = 0; e < 4; e++){
            int c = (c4<<2) + e;
            int ln = lb + (c & 3);
            int j  = (c >> 2) & 1;
            Bp[(((c >> 3)*NT8 + nt)*32 + ln)*2 + j] = tf32r(vp[e]);
        }
    }
}

// ---------------- warp mma over one K=32 slab ----------------
template<int MT, int NT, int NTTOT>
__device__ __forceinline__ void wmma_slab(const float* Ap, const float* Bp,
                                          float4* acc, int wm, int wn, int lane){
    #pragma unroll
    for (int kc = 0; kc < 4; kc++){
        uint4 a[MT]; uint2 b[NT];
        #pragma unroll
        for (int m = 0; m < MT; m++)
            a[m] = ((const uint4*)Ap)[((kc<<3) + wm*MT + m)*32 + lane];
        #pragma unroll
        for (int n = 0; n < NT; n++)
            b[n] = ((const uint2*)Bp)[(kc*NTTOT + wn*NT + n)*32 + lane];
        #pragma unroll
        for (int m = 0; m < MT; m++)
            #pragma unroll
            for (int n = 0; n < NT; n++)
                mma8(acc[m*NT + n], a[m], b[n]);
    }
}

// ---------------- rmsnorm: h -> z ----------------
__global__ __launch_bounds__(256)
void rms_k(const float* __restrict__ h, float* __restrict__ z){
    int warp = threadIdx.x >> 5, lane = threadIdx.x & 31;
    size_t tok = (size_t)blockIdx.x*8 + warp;
    const float4* hr = (const float4*)(h + tok*1024);
    float4 v[8]; float ss = 0.f;
    #pragma unroll
    for (int j = 0; j < 8; j++){
        v[j] = hr[lane + 32*j];
        ss += v[j].x*v[j].x + v[j].y*v[j].y + v[j].z*v[j].z + v[j].w*v[j].w;
    }
    #pragma unroll
    for (int o = 16; o; o >>= 1) ss += __shfl_xor_sync(0xffffffffu, ss, o);
    float sc = rsqrtf(ss*(1.f/1024.f) + EPSRMS);
    float4* zr = (float4*)(z + tok*1024);
    #pragma unroll
    for (int j = 0; j < 8; j++){
        float4 w = v[j];
        w.x *= sc; w.y *= sc; w.z *= sc; w.w *= sc;
        zr[lane + 32*j] = w;
    }
}

// ---------------- low-rank projection: P = combined . [B1;B2]^T ----------------
// P[t][0:32] from B1, P[t][32:64] from B2. halves=2 -> K spans z and shifted z.
__global__ __launch_bounds__(256)
void p_k(const float* __restrict__ z, float* __restrict__ P,
         const float* __restrict__ B1, const float* __restrict__ B2,
         int halves, int ldB){
    extern __shared__ float sm[];
    float* Ap = sm;            // 4096 floats
    float* Bp = sm + 4096;     // 2048 floats (64 rows)
    int tid = threadIdx.x, warp = tid >> 5, lane = tid & 31;
    int wm = warp >> 1, wn = warp & 1;
    int batch = blockIdx.x >> 4, seq0 = (blockIdx.x & 15) << 7;
    const float* zb = z + (size_t)batch*2048*1024;

    float4 acc[8];
    #pragma unroll
    for (int i = 0; i < 8; i++) acc[i] = make_float4(0.f,0.f,0.f,0.f);

    int nslab = halves << 5;
    for (int s = 0; s < nslab; s++){
        int half = s >> 5, colbase = (s & 31) << 5;
        fillA_tok(Ap, zb, seq0, half, colbase, tid);
        for (int i = tid; i < 512; i += 256){
            int n = i >> 3, c4 = i & 7;
            const float* src = ((n < 32) ? B1 : B2)
                             + (size_t)(n & 31)*ldB + half*1024 + colbase + (c4<<2);
            float4 v = *(const float4*)src;
            const float* vp = &v.x;
            int nt = n >> 3, lb = (n & 7) << 2;
            #pragma unroll
            for (int e = 0; e < 4; e++){
                int c = (c4<<2) + e;
                int ln = lb + (c & 3), j = (c >> 2) & 1;
                Bp[(((c >> 3)*8 + nt)*32 + ln)*2 + j] = tf32r(vp[e]);
            }
        }
        __syncthreads();
        wmma_slab<2,4,8>(Ap, Bp, acc, wm, wn, lane);
        __syncthreads();
    }

    size_t tokbase = (size_t)batch*2048 + seq0;
    #pragma unroll
    for (int m = 0; m < 2; m++)
        #pragma unroll
        for (int n = 0; n < 4; n++){
            int r0  = wm*32 + m*16 + (lane >> 2);
            int col = wn*32 + n*8 + (lane & 3)*2;
            float4 d = acc[m*4 + n];
            *(float2*)(P + (tokbase + r0    )*64 + col) = make_float2(d.x, d.y);
            *(float2*)(P + (tokbase + r0 + 8)*64 + col) = make_float2(d.z, d.w);
        }
}

// ---------------- iteration main GEMM ----------------
// D_g = z_slice.Wg^T + P[:,0:32].Ag^T ; D_u analogous. hout = hin + sigm(D_g)*D_u
__global__ __launch_bounds__(256)
void main_k(const float* __restrict__ z, const float* __restrict__ P,
            const float* __restrict__ hin, float* __restrict__ hout,
            const float* __restrict__ Wg, const float* __restrict__ Wu,
            const float* __restrict__ Ag, const float* __restrict__ Au){
    extern __shared__ float sm[];
    float* Ap = sm;
    float* Bg = sm + 4096;
    float* Bu = sm + 8192;
    int tid = threadIdx.x, warp = tid >> 5, lane = tid & 31;
    int wm = warp >> 1, wn = warp & 1;
    int batch = blockIdx.x >> 4, seq0 = (blockIdx.x & 15) << 7;
    int nblk = blockIdx.y;
    const float* zb = z + (size_t)batch*2048*1024;
    int shift = (nblk >= 4) ? 1 : 0;
    int colbase0 = (nblk & 3) << 8;
    size_t tok0 = (size_t)batch*2048 + seq0;

    float4 accg[16], accu[16];
    #pragma unroll
    for (int i = 0; i < 16; i++){
        accg[i] = make_float4(0.f,0.f,0.f,0.f);
        accu[i] = make_float4(0.f,0.f,0.f,0.f);
    }

    for (int s = 0; s < 10; s++){
        if (s < 8){
            fillA_tok(Ap, zb, seq0, shift, colbase0 + (s<<5), tid);
            fillB(Bg, Wg + (size_t)(nblk*128)*256 + (s<<5), 256, 128, tid);
            fillB(Bu, Wu + (size_t)(nblk*128)*256 + (s<<5), 256, 128, tid);
        } else if (s == 8){
            fillA(Ap, P + tok0*64, 64, tid);
            fillB(Bg, Ag + (size_t)(nblk*128)*32, 32, 128, tid);
        } else {
            fillA(Ap, P + tok0*64 + 32, 64, tid);
            fillB(Bu, Au + (size_t)(nblk*128)*32, 32, 128, tid);
        }
        __syncthreads();
        if (s < 8){
            wmma_slab<2,8,16>(Ap, Bg, accg, wm, wn, lane);
            wmma_slab<2,8,16>(Ap, Bu, accu, wm, wn, lane);
        } else if (s == 8){
            wmma_slab<2,8,16>(Ap, Bg, accg, wm, wn, lane);
        } else {
            wmma_slab<2,8,16>(Ap, Bu, accu, wm, wn, lane);
        }
        __syncthreads();
    }

    #pragma unroll
    for (int m = 0; m < 2; m++)
        #pragma unroll
        for (int n = 0; n < 8; n++){
            int r0   = wm*32 + m*16 + (lane >> 2);
            int gcol = nblk*128 + wn*64 + n*8 + (lane & 3)*2;
            float4 dg = accg[m*8 + n], du = accu[m*8 + n];
            size_t ta = tok0 + r0, tb = tok0 + r0 + 8;
            float2 ha = *(const float2*)(hin + ta*1024 + gcol);
            float2 hb = *(const float2*)(hin + tb*1024 + gcol);
            float2 oa, ob;
            oa.x = fmaf(sigm(dg.x), du.x, ha.x);
            oa.y = fmaf(sigm(dg.y), du.y, ha.y);
            ob.x = fmaf(sigm(dg.z), du.z, hb.x);
            ob.y = fmaf(sigm(dg.w), du.w, hb.y);
            *(float2*)(hout + ta*1024 + gcol) = oa;
            *(float2*)(hout + tb*1024 + gcol) = ob;
        }
}

// ---------------- ff GEMMs (ffg raw store; fff fused silu*mul) ----------------
// mode 0: out raw accums to g_ffg (W=ffg_W, A=ffg_A, pofs=0)
// mode 1: read g from g_ffg, write silu(g)*f to g_ff (W=fff_W, A=fff_A, pofs=32)
__global__ __launch_bounds__(256)
void ff_k(const float* __restrict__ z, const float* __restrict__ P,
          const float* __restrict__ W, const float* __restrict__ Alr,
          int pofs, int mode){
    extern __shared__ float sm[];
    float* Ap = sm;
    float* Bp = sm + 4096;       // 176*32 = 5632 floats
    int tid = threadIdx.x, warp = tid >> 5, lane = tid & 31;
    int wm = warp >> 1, wn = warp & 1;
    size_t tok0 = (size_t)blockIdx.x*128;
    int nblk = blockIdx.y, nsub = blockIdx.z;
    int n0 = nblk*352 + nsub*176;

    float4 acc[22];
    #pragma unroll
    for (int i = 0; i < 22; i++) acc[i] = make_float4(0.f,0.f,0.f,0.f);

    for (int s = 0; s < 5; s++){
        if (s < 4){
            fillA(Ap, z + tok0*1024 + nblk*128 + (s<<5), 1024, tid);
            fillB(Bp, W + (size_t)n0*128 + (s<<5), 128, 176, tid);
        } else {
            fillA(Ap, P + tok0*64 + pofs, 64, tid);
            fillB(Bp, Alr + (size_t)n0*32, 32, 176, tid);
        }
        __syncthreads();
        wmma_slab<2,11,22>(Ap, Bp, acc, wm, wn, lane);
        __syncthreads();
    }

    #pragma unroll
    for (int m = 0; m < 2; m++)
        #pragma unroll
        for (int n = 0; n < 11; n++){
            int r0  = wm*32 + m*16 + (lane >> 2);
            int col = n0 + wn*88 + n*8 + (lane & 3)*2;
            float4 d = acc[m*11 + n];
            size_t ia = (tok0 + r0)*2816 + col;
            size_t ib = (tok0 + r0 + 8)*2816 + col;
            if (mode == 0){
                *(float2*)(g_ffg + ia) = make_float2(d.x, d.y);
                *(float2*)(g_ffg + ib) = make_float2(d.z, d.w);
            } else {
                float2 ga = *(const float2*)(g_ffg + ia);
                float2 gb = *(const float2*)(g_ffg + ib);
                float2 oa, ob;
                oa.x = ga.x*sigm(ga.x)*d.x;
                oa.y = ga.y*sigm(ga.y)*d.y;
                ob.x = gb.x*sigm(gb.x)*d.z;
                ob.y = gb.y*sigm(gb.y)*d.w;
                *(float2*)(g_ff + ia) = oa;
                *(float2*)(g_ff + ib) = ob;
            }
        }
}

// ---------------- Pp = ff . ffp_B^T (N=32, K=2816) ----------------
__global__ __launch_bounds__(256)
void pp_k(const float* __restrict__ ffpB){
    extern __shared__ float sm[];
    float* Ap = sm;
    float* Bp = sm + 4096;       // 32*32*... = 1024*2 floats -> 2048
    int tid = threadIdx.x, warp = tid >> 5, lane = tid & 31;
    size_t tok0 = (size_t)blockIdx.x*128;

    float4 acc[4];
    #pragma unroll
    for (int i = 0; i < 4; i++) acc[i] = make_float4(0.f,0.f,0.f,0.f);

    for (int s = 0; s < 88; s++){
        fillA(Ap, g_ff + tok0*2816 + (s<<5), 2816, tid);
        fillB(Bp, ffpB + (s<<5), 2816, 32, tid);
        __syncthreads();
        wmma_slab<1,4,4>(Ap, Bp, acc, warp, 0, lane);
        __syncthreads();
    }

    #pragma unroll
    for (int n = 0; n < 4; n++){
        int r0  = warp*16 + (lane >> 2);
        int col = n*8 + (lane & 3)*2;
        float4 d = acc[n];
        *(float2*)(g_Pp + (tok0 + r0    )*32 + col) = make_float2(d.x, d.y);
        *(float2*)(g_Pp + (tok0 + r0 + 8)*32 + col) = make_float2(d.z, d.w);
    }
}

// ---------------- out = h + ffp(ff) ----------------
__global__ __launch_bounds__(256)
void out_k(const float* __restrict__ hin, float* __restrict__ out,
           const float* __restrict__ Wp, const float* __restrict__ Ap_lr){
    extern __shared__ float sm[];
    float* Ap = sm;
    float* Bp = sm + 4096;
    int tid = threadIdx.x, warp = tid >> 5, lane = tid & 31;
    int wm = warp >> 1, wn = warp & 1;
    size_t tok0 = (size_t)blockIdx.x*128;
    int nblk = blockIdx.y;

    float4 acc[16];
    #pragma unroll
    for (int i = 0; i < 16; i++) acc[i] = make_float4(0.f,0.f,0.f,0.f);

    for (int s = 0; s < 12; s++){
        if (s < 11){
            fillA(Ap, g_ff + tok0*2816 + nblk*352 + (s<<5), 2816, tid);
            fillB(Bp, Wp + (size_t)(nblk*128)*352 + (s<<5), 352, 128, tid);
        } else {
            fillA(Ap, g_Pp + tok0*32, 32, tid);
            fillB(Bp, Ap_lr + (size_t)(nblk*128)*32, 32, 128, tid);
        }
        __syncthreads();
        wmma_slab<2,8,16>(Ap, Bp, acc, wm, wn, lane);
        __syncthreads();
    }

    #pragma unroll
    for (int m = 0; m < 2; m++)
        #pragma unroll
        for (int n = 0; n < 8; n++){
            int r0   = wm*32 + m*16 + (lane >> 2);
            int gcol = nblk*128 + wn*64 + n*8 + (lane & 3)*2;
            float4 d = acc[m*8 + n];
            size_t ta = tok0 + r0, tb = tok0 + r0 + 8;
            float2 ha = *(const float2*)(hin + ta*1024 + gcol);
            float2 hb = *(const float2*)(hin + tb*1024 + gcol);
            float2 oa = make_float2(ha.x + d.x, ha.y + d.y);
            float2 ob = make_float2(hb.x + d.z, hb.y + d.w);
            *(float2*)(out + ta*1024 + gcol) = oa;
            *(float2*)(out + tb*1024 + gcol) = ob;
        }
}

// ---------------- launcher ----------------
template <typename T>
static float* symaddr(const T& s){
    void* p = nullptr;
    cudaGetSymbolAddress(&p, s);
    return (float*)p;
}

extern "C" void kernel_launch(void* const* d_in, const int* in_sizes, int n_in,
                              void* d_out, int out_size) {
    const float* x     = (const float*)d_in[0];
    const float* fg_W  = (const float*)d_in[1];
    const float* fg_A  = (const float*)d_in[2];
    const float* fg_B  = (const float*)d_in[3];
    const float* gu_W  = (const float*)d_in[4];
    const float* gu_A  = (const float*)d_in[5];
    const float* gu_B  = (const float*)d_in[6];
    const float* ffg_W = (const float*)d_in[7];
    const float* ffg_A = (const float*)d_in[8];
    const float* ffg_B = (const float*)d_in[9];
    const float* fff_W = (const float*)d_in[10];
    const float* fff_A = (const float*)d_in[11];
    const float* fff_B = (const float*)d_in[12];
    const float* ffp_W = (const float*)d_in[13];
    const float* ffp_A = (const float*)d_in[14];
    const float* ffp_B = (const float*)d_in[15];
    float* out = (float*)d_out;

    float* z  = symaddr(g_z);
    float* h0 = symaddr(g_h0);
    float* h1 = symaddr(g_h1);
    float* P  = symaddr(g_P);

    const int SM_P    = (4096 + 2048) * 4;            // 24 KB
    const int SM_MAIN = (4096 * 3) * 4;               // 48 KB
    const int SM_FF   = (4096 + 5632) * 4;            // ~38 KB
    const int SM_PP   = (4096 + 2048) * 4;            // 24 KB
    const int SM_OUT  = (4096 * 2) * 4;               // 32 KB
    cudaFuncSetAttribute(main_k, cudaFuncAttributeMaxDynamicSharedMemorySize, SM_MAIN);
    cudaFuncSetAttribute(ff_k,   cudaFuncAttributeMaxDynamicSharedMemorySize, SM_FF);

    const float* hcur = x;
    float* bufs[2] = {h0, h1};
    for (int it = 0; it < 4; it++){
        float* hnext = bufs[it & 1];
        rms_k<<<2048, 256>>>(hcur, z);
        p_k<<<128, 256, SM_P>>>(z, P, fg_B, gu_B, 2, 2048);
        main_k<<<dim3(128, 8), 256, SM_MAIN>>>(z, P, hcur, hnext,
                                               fg_W, gu_W, fg_A, gu_A);
        hcur = hnext;
    }
    rms_k<<<2048, 256>>>(hcur, z);
    p_k<<<128, 256, SM_P>>>(z, P, ffg_B, fff_B, 1, 1024);
    ff_k<<<dim3(128, 8, 2), 256, SM_FF>>>(z, P, ffg_W, ffg_A, 0, 0);
    ff_k<<<dim3(128, 8, 2), 256, SM_FF>>>(z, P, fff_W, fff_A, 32, 1);
    pp_k<<<128, 256, SM_PP>>>(ffp_B);
    out_k<<<dim3(128, 8), 256, SM_OUT>>>(hcur, out, ffp_W, ffp_A);
}

// round 7
// speedup vs baseline: 5.0386x; 2.9180x over previous
#include <cuda_runtime.h>
#include <cstdint>
#include <cstddef>

#define EPSRMS 1.1920929e-07f

// ---------------- persistent device scratch ----------------
__device__ float g_z  [16777216];
__device__ float g_h0 [16777216];
__device__ float g_h1 [16777216];
__device__ float g_P  [16384*64];
__device__ float g_Pp [16384*32];
__device__ float g_ffg[16384*2816];
__device__ float g_ff [16384*2816];
__device__ float g_part[8*16384*64];
__device__ float g_wb [2170880];          // tf32-rounded weight copies

// weight offsets inside g_wb
#define W_FGW  0
#define W_GUW  262144
#define W_FGA  524288
#define W_GUA  557056
#define W_FGB  589824
#define W_GUB  655360
#define W_FFGW 720896
#define W_FFGA 1081344
#define W_FFGB 1171456
#define W_FFFW 1204224
#define W_FFFA 1564672
#define W_FFFB 1654784
#define W_FFPW 1687552
#define W_FFPA 2048000
#define W_FFPB 2080768

// ---------------- helpers ----------------
__device__ __forceinline__ float sigm(float x){ return 1.0f/(1.0f+__expf(-x)); }

__device__ __forceinline__ float tf32r(float x){
    uint32_t u;
    asm("cvt.rna.tf32.f32 %0, %1;" : "=r"(u) : "f"(x));
    return __uint_as_float(u);
}

__device__ __forceinline__ uint32_t smem_u32(const void* p){
    uint32_t a;
    asm("{ .reg .u64 t; cvta.to.shared.u64 t, %1; cvt.u32.u64 %0, t; }" : "=r"(a) : "l"(p));
    return a;
}

__device__ __forceinline__ void mma8(float4& d, uint4 a, uint2 b){
    asm volatile(
        "mma.sync.aligned.m16n8k8.row.col.f32.tf32.tf32.f32 "
        "{%0,%1,%2,%3},{%4,%5,%6,%7},{%8,%9},{%0,%1,%2,%3};"
        : "+f"(d.x), "+f"(d.y), "+f"(d.z), "+f"(d.w)
        : "r"(a.x), "r"(a.y), "r"(a.z), "r"(a.w), "r"(b.x), "r"(b.y));
}

__device__ __forceinline__ void cp16(uint32_t dst, const float* src, int sz){
    asm volatile("cp.async.ca.shared.global [%0], [%1], 16, %2;"
                 :: "r"(dst), "l"(src), "r"(sz) : "memory");
}
#define CPCOMMIT() asm volatile("cp.async.commit_group;" ::: "memory")
#define CPWAIT1()  asm volatile("cp.async.wait_group 1;"  ::: "memory")

// ---------------- smem staging (row-major, XOR-swizzled 16B chunks) ----------------
// row r, chunk c4(0..7): byte offset = r*128 + ((c4 ^ (r&7))<<4)
template<int NCHUNK>   // NCHUNK = rows*8
__device__ __forceinline__ void stage_tile(uint32_t sb, const float* src, size_t ld){
    int tid = threadIdx.x;
    #pragma unroll
    for (int i = 0; i < (NCHUNK + 255)/256; i++){
        int idx = tid + i*256;
        if ((NCHUNK & 255) && idx >= NCHUNK) continue;
        int r = idx >> 3, c4 = idx & 7;
        cp16(sb + r*128 + ((uint32_t)(c4 ^ (r & 7)) << 4),
             src + (size_t)r*ld + (c4 << 2), 16);
    }
}

// A slab from token rows of z, with causal shift (token = seq0+r-shift; zeros if <0)
__device__ __forceinline__ void stage_tok(uint32_t sb, const float* zb,
                                          int seq0, int shift, int col){
    int tid = threadIdx.x;
    #pragma unroll
    for (int i = 0; i < 4; i++){
        int idx = tid + i*256;
        int r = idx >> 3, c4 = idx & 7;
        int s = seq0 + r - shift;
        int sz = (s >= 0) ? 16 : 0;
        if (s < 0) s = 0;
        cp16(sb + r*128 + ((uint32_t)(c4 ^ (r & 7)) << 4),
             zb + (size_t)s*1024 + col + (c4 << 2), sz);
    }
}

// ---------------- fragment compute over one K=32 slab ----------------
// per-thread: row part lr=lane>>2, col part lc=lane&3, swizzle mask xm=lane&28
template<int MT, int NT>
__device__ __forceinline__ void comp_slab(const float* sA, const float* sB, float4* acc,
                                          int mb0, int nb0, int lane){
    int lr = lane >> 2, xm = lane & 28, lc = lane & 3;
    #pragma unroll
    for (int kc = 0; kc < 4; kc++){
        int ci = ((kc << 3) | lc) ^ xm;
        int ci4 = ci ^ 4;
        uint4 a[MT];
        #pragma unroll
        for (int m = 0; m < MT; m++){
            const float* ap = sA + (mb0 + m*16 + lr)*32;
            a[m].x = __float_as_uint(ap[ci]);
            a[m].y = __float_as_uint(ap[256 + ci]);
            a[m].z = __float_as_uint(ap[ci4]);
            a[m].w = __float_as_uint(ap[256 + ci4]);
        }
        #pragma unroll
        for (int n = 0; n < NT; n++){
            const float* bp = sB + (nb0 + n*8 + lr)*32;
            uint2 b;
            b.x = __float_as_uint(bp[ci]);
            b.y = __float_as_uint(bp[ci4]);
            #pragma unroll
            for (int m = 0; m < MT; m++) mma8(acc[m*NT + n], a[m], b);
        }
    }
}

// dual-B variant (shares A fragment loads)
template<int MT, int NT>
__device__ __forceinline__ void comp_slab2(const float* sA, const float* sB1, const float* sB2,
                                           float4* acc1, float4* acc2,
                                           int mb0, int nb0, int lane){
    int lr = lane >> 2, xm = lane & 28, lc = lane & 3;
    #pragma unroll
    for (int kc = 0; kc < 4; kc++){
        int ci = ((kc << 3) | lc) ^ xm;
        int ci4 = ci ^ 4;
        uint4 a[MT];
        #pragma unroll
        for (int m = 0; m < MT; m++){
            const float* ap = sA + (mb0 + m*16 + lr)*32;
            a[m].x = __float_as_uint(ap[ci]);
            a[m].y = __float_as_uint(ap[256 + ci]);
            a[m].z = __float_as_uint(ap[ci4]);
            a[m].w = __float_as_uint(ap[256 + ci4]);
        }
        #pragma unroll
        for (int n = 0; n < NT; n++){
            const float* b1p = sB1 + (nb0 + n*8 + lr)*32;
            const float* b2p = sB2 + (nb0 + n*8 + lr)*32;
            uint2 b1, b2;
            b1.x = __float_as_uint(b1p[ci]);  b1.y = __float_as_uint(b1p[ci4]);
            b2.x = __float_as_uint(b2p[ci]);  b2.y = __float_as_uint(b2p[ci4]);
            #pragma unroll
            for (int m = 0; m < MT; m++){
                mma8(acc1[m*NT + n], a[m], b1);
                mma8(acc2[m*NT + n], a[m], b2);
            }
        }
    }
}

// ---------------- weight tf32 pre-rounding ----------------
__global__ void cvt_k(const float* p0, const float* p1, const float* p2, const float* p3,
                      const float* p4, const float* p5, const float* p6, const float* p7,
                      const float* p8, const float* p9, const float* p10, const float* p11,
                      const float* p12, const float* p13, const float* p14){
    const float* srcs[15] = {p0,p1,p2,p3,p4,p5,p6,p7,p8,p9,p10,p11,p12,p13,p14};
    const int sz4[15] = {65536,65536,8192,8192,16384,16384,90112,22528,8192,
                         90112,22528,8192,90112,8192,22528};
    const int off[15] = {W_FGW,W_GUW,W_FGA,W_GUA,W_FGB,W_GUB,W_FFGW,W_FFGA,W_FFGB,
                         W_FFFW,W_FFFA,W_FFFB,W_FFPW,W_FFPA,W_FFPB};
    int t = blockIdx.y;
    int i = blockIdx.x*256 + threadIdx.x;
    if (i >= sz4[t]) return;
    float4 v = ((const float4*)srcs[t])[i];
    v.x = tf32r(v.x); v.y = tf32r(v.y); v.z = tf32r(v.z); v.w = tf32r(v.w);
    ((float4*)(g_wb + off[t]))[i] = v;
}

// ---------------- rmsnorm: h -> z (tf32-rounded output) ----------------
__global__ __launch_bounds__(256)
void rms_k(const float* __restrict__ h, float* __restrict__ z){
    int warp = threadIdx.x >> 5, lane = threadIdx.x & 31;
    size_t tok = (size_t)blockIdx.x*8 + warp;
    const float4* hr = (const float4*)(h + tok*1024);
    float4 v[8]; float ss = 0.f;
    #pragma unroll
    for (int j = 0; j < 8; j++){
        v[j] = hr[lane + 32*j];
        ss += v[j].x*v[j].x + v[j].y*v[j].y + v[j].z*v[j].z + v[j].w*v[j].w;
    }
    #pragma unroll
    for (int o = 16; o; o >>= 1) ss += __shfl_xor_sync(0xffffffffu, ss, o);
    float sc = rsqrtf(ss*(1.f/1024.f) + EPSRMS);
    float4* zr = (float4*)(z + tok*1024);
    #pragma unroll
    for (int j = 0; j < 8; j++){
        float4 w;
        w.x = tf32r(v[j].x*sc); w.y = tf32r(v[j].y*sc);
        w.z = tf32r(v[j].z*sc); w.w = tf32r(v[j].w*sc);
        zr[lane + 32*j] = w;
    }
}

// ---------------- low-rank projection partials ----------------
// grid (128, nch); chunk covers K=256; partial [128tok x 64] -> g_part[chunk]
__global__ __launch_bounds__(256)
void p_k(const float* __restrict__ z, const float* __restrict__ B1,
         const float* __restrict__ B2, int halves, int ldB){
    extern __shared__ float sm[];
    uint32_t sb = smem_u32(sm);
    int tid = threadIdx.x, warp = tid >> 5, lane = tid & 31;
    int wm = warp >> 1, wn = warp & 1;
    int tile = blockIdx.x, chunk = blockIdx.y;
    int batch = tile >> 4, seq0 = (tile & 15) << 7;
    const float* zb = z + (size_t)batch*2048*1024;
    int half = (halves == 2) ? (chunk >> 2) : 0;
    int colbase = ((halves == 2) ? (chunk & 3) : chunk) << 8;
    int koff = half*1024 + colbase;

    float4 acc[8];
    #pragma unroll
    for (int i = 0; i < 8; i++) acc[i] = make_float4(0.f,0.f,0.f,0.f);

    auto fill = [&](int s, int buf){
        uint32_t aB = sb + (uint32_t)buf*24576u;
        uint32_t bB = aB + 16384u;
        stage_tok(aB, zb, seq0, half, colbase + (s << 5));
        int ko = koff + (s << 5);
        #pragma unroll
        for (int i = 0; i < 2; i++){
            int idx = tid + i*256;
            int r = idx >> 3, c4 = idx & 7;
            const float* src = ((r < 32) ? B1 : B2) + (size_t)(r & 31)*ldB + ko + (c4 << 2);
            cp16(bB + r*128 + ((uint32_t)(c4 ^ (r & 7)) << 4), src, 16);
        }
    };

    fill(0, 0); CPCOMMIT();
    for (int s = 0; s < 8; s++){
        if (s < 7) fill(s + 1, (s + 1) & 1);
        CPCOMMIT(); CPWAIT1(); __syncthreads();
        const float* base = sm + (s & 1)*6144;
        comp_slab<2,4>(base, base + 4096, acc, wm*32, wn*32, lane);
        __syncthreads();
    }

    size_t tok0 = (size_t)tile*128;
    float* dst = g_part + (size_t)chunk*1048576u;
    int lr = lane >> 2, lc2 = (lane & 3)*2;
    #pragma unroll
    for (int m = 0; m < 2; m++)
        #pragma unroll
        for (int n = 0; n < 4; n++){
            int r0 = wm*32 + m*16 + lr;
            int col = wn*32 + n*8 + lc2;
            float4 d = acc[m*4 + n];
            *(float2*)(dst + (tok0 + r0    )*64 + col) = make_float2(d.x, d.y);
            *(float2*)(dst + (tok0 + r0 + 8)*64 + col) = make_float2(d.z, d.w);
        }
}

// reduce partials (+ tf32 round)
__global__ void pred_k(float* __restrict__ dst, const float* __restrict__ src,
                       int nch, size_t cstride, int n4){
    int i = blockIdx.x*256 + threadIdx.x;
    if (i >= n4) return;
    float4 a = ((const float4*)src)[i];
    for (int c = 1; c < nch; c++){
        float4 v = ((const float4*)(src + (size_t)c*cstride))[i];
        a.x += v.x; a.y += v.y; a.z += v.z; a.w += v.w;
    }
    a.x = tf32r(a.x); a.y = tf32r(a.y); a.z = tf32r(a.z); a.w = tf32r(a.w);
    ((float4*)dst)[i] = a;
}

// ---------------- iteration main GEMM ----------------
// grid (128, 16): nblk = by>>1 (diag block), nh = by&1 (64-col half)
__global__ __launch_bounds__(256)
void main_k(const float* __restrict__ z, const float* __restrict__ P,
            const float* __restrict__ hin, float* __restrict__ hout,
            const float* __restrict__ Wg, const float* __restrict__ Wu,
            const float* __restrict__ Ag, const float* __restrict__ Au){
    extern __shared__ float sm[];
    uint32_t sb = smem_u32(sm);
    int tid = threadIdx.x, warp = tid >> 5, lane = tid & 31;
    int wm = warp >> 1, wn = warp & 1;
    int tile = blockIdx.x, nb2 = blockIdx.y;
    int nblk = nb2 >> 1, nh = nb2 & 1;
    int batch = tile >> 4, seq0 = (tile & 15) << 7;
    const float* zb = z + (size_t)batch*2048*1024;
    int shift = (nblk >= 4) ? 1 : 0;
    int colbase0 = (nblk & 3) << 8;
    size_t tok0 = (size_t)tile*128;
    int wrow0 = nblk*128 + nh*64;

    float4 accg[8], accu[8];
    #pragma unroll
    for (int i = 0; i < 8; i++){
        accg[i] = make_float4(0.f,0.f,0.f,0.f);
        accu[i] = make_float4(0.f,0.f,0.f,0.f);
    }

    auto fill = [&](int s, int buf){
        uint32_t aB = sb + (uint32_t)buf*32768u;
        uint32_t gB = aB + 16384u, uB = aB + 24576u;
        if (s < 8){
            stage_tok(aB, zb, seq0, shift, colbase0 + (s << 5));
            const float* g = Wg + (size_t)wrow0*256 + (s << 5);
            const float* u = Wu + (size_t)wrow0*256 + (s << 5);
            #pragma unroll
            for (int i = 0; i < 2; i++){
                int idx = tid + i*256;
                int r = idx >> 3, c4 = idx & 7;
                uint32_t so = r*128 + ((uint32_t)(c4 ^ (r & 7)) << 4);
                cp16(gB + so, g + (size_t)r*256 + (c4 << 2), 16);
                cp16(uB + so, u + (size_t)r*256 + (c4 << 2), 16);
            }
        } else {
            int isg = (s == 8);
            stage_tile<1024>(aB, P + tok0*64 + (isg ? 0 : 32), 64);
            stage_tile<512>(isg ? gB : uB,
                            (isg ? Ag : Au) + (size_t)wrow0*32, 32);
        }
    };

    fill(0, 0); CPCOMMIT();
    for (int s = 0; s < 10; s++){
        if (s < 9) fill(s + 1, (s + 1) & 1);
        CPCOMMIT(); CPWAIT1(); __syncthreads();
        const float* base = sm + (s & 1)*8192;
        const float* sA = base;
        const float* sBg = base + 4096;
        const float* sBu = base + 6144;
        if (s < 8)
            comp_slab2<2,4>(sA, sBg, sBu, accg, accu, wm*32, wn*32, lane);
        else if (s == 8)
            comp_slab<2,4>(sA, sBg, accg, wm*32, wn*32, lane);
        else
            comp_slab<2,4>(sA, sBu, accu, wm*32, wn*32, lane);
        __syncthreads();
    }

    int lr = lane >> 2, lc2 = (lane & 3)*2;
    #pragma unroll
    for (int m = 0; m < 2; m++)
        #pragma unroll
        for (int n = 0; n < 4; n++){
            int r0 = wm*32 + m*16 + lr;
            int col = wrow0 + wn*32 + n*8 + lc2;
            float4 dg = accg[m*4 + n], du = accu[m*4 + n];
            size_t ta = tok0 + r0, tb = ta + 8;
            float2 ha = *(const float2*)(hin + ta*1024 + col);
            float2 hb = *(const float2*)(hin + tb*1024 + col);
            float2 oa, ob;
            oa.x = fmaf(sigm(dg.x), du.x, ha.x);
            oa.y = fmaf(sigm(dg.y), du.y, ha.y);
            ob.x = fmaf(sigm(dg.z), du.z, hb.x);
            ob.y = fmaf(sigm(dg.w), du.w, hb.y);
            *(float2*)(hout + ta*1024 + col) = oa;
            *(float2*)(hout + tb*1024 + col) = ob;
        }
}

// ---------------- ff GEMM (mode0: raw ffg; mode1: silu(ffg)*fff -> g_ff) ----------------
__global__ __launch_bounds__(256)
void ff_k(const float* __restrict__ z, const float* __restrict__ P,
          const float* __restrict__ W, const float* __restrict__ Alr,
          int pofs, int mode){
    extern __shared__ float sm[];
    uint32_t sb = smem_u32(sm);
    int tid = threadIdx.x, warp = tid >> 5, lane = tid & 31;
    int wm = warp >> 1, wn = warp & 1;
    int tile = blockIdx.x, nblk = blockIdx.y, nsub = blockIdx.z;
    int n0 = nblk*352 + nsub*176;
    size_t tok0 = (size_t)tile*128;

    float4 acc[22];
    #pragma unroll
    for (int i = 0; i < 22; i++) acc[i] = make_float4(0.f,0.f,0.f,0.f);

    auto fill = [&](int s, int buf){
        uint32_t aB = sb + (uint32_t)buf*38912u;
        uint32_t bB = aB + 16384u;
        if (s < 4){
            stage_tile<1024>(aB, z + tok0*1024 + nblk*128 + (s << 5), 1024);
            stage_tile<1408>(bB, W + (size_t)n0*128 + (s << 5), 128);
        } else {
            stage_tile<1024>(aB, P + tok0*64 + pofs, 64);
            stage_tile<1408>(bB, Alr + (size_t)n0*32, 32);
        }
    };

    fill(0, 0); CPCOMMIT();
    for (int s = 0; s < 5; s++){
        if (s < 4) fill(s + 1, (s + 1) & 1);
        CPCOMMIT(); CPWAIT1(); __syncthreads();
        const float* base = sm + (s & 1)*9728;
        comp_slab<2,11>(base, base + 4096, acc, wm*32, wn*88, lane);
        __syncthreads();
    }

    int lr = lane >> 2, lc2 = (lane & 3)*2;
    #pragma unroll
    for (int m = 0; m < 2; m++)
        #pragma unroll
        for (int n = 0; n < 11; n++){
            int r0 = wm*32 + m*16 + lr;
            int col = n0 + wn*88 + n*8 + lc2;
            float4 d = acc[m*11 + n];
            size_t ia = (tok0 + r0)*2816 + col;
            size_t ib = (tok0 + r0 + 8)*2816 + col;
            if (mode == 0){
                *(float2*)(g_ffg + ia) = make_float2(d.x, d.y);
                *(float2*)(g_ffg + ib) = make_float2(d.z, d.w);
            } else {
                float2 ga = *(const float2*)(g_ffg + ia);
                float2 gb = *(const float2*)(g_ffg + ib);
                float2 oa, ob;
                oa.x = tf32r(ga.x*sigm(ga.x)*d.x);
                oa.y = tf32r(ga.y*sigm(ga.y)*d.y);
                ob.x = tf32r(gb.x*sigm(gb.x)*d.z);
                ob.y = tf32r(gb.y*sigm(gb.y)*d.w);
                *(float2*)(g_ff + ia) = oa;
                *(float2*)(g_ff + ib) = ob;
            }
        }
}

// ---------------- Pp partials: ff . ffp_B^T, K-split 8 x 352 ----------------
__global__ __launch_bounds__(256)
void pp_k(const float* __restrict__ ffpB){
    extern __shared__ float sm[];
    uint32_t sb = smem_u32(sm);
    int tid = threadIdx.x, warp = tid >> 5, lane = tid & 31;
    int wm = warp >> 1, wn = warp & 1;
    int tile = blockIdx.x, chunk = blockIdx.y;
    size_t tok0 = (size_t)tile*128;

    float4 acc[4];
    #pragma unroll
    for (int i = 0; i < 4; i++) acc[i] = make_float4(0.f,0.f,0.f,0.f);

    auto fill = [&](int s, int buf){
        uint32_t aB = sb + (uint32_t)buf*20480u;
        uint32_t bB = aB + 16384u;
        stage_tile<1024>(aB, g_ff + tok0*2816 + chunk*352 + (s << 5), 2816);
        stage_tile<256>(bB, ffpB + chunk*352 + (s << 5), 2816);
    };

    fill(0, 0); CPCOMMIT();
    for (int s = 0; s < 11; s++){
        if (s < 10) fill(s + 1, (s + 1) & 1);
        CPCOMMIT(); CPWAIT1(); __syncthreads();
        const float* base = sm + (s & 1)*5120;
        comp_slab<2,2>(base, base + 4096, acc, wm*32, wn*16, lane);
        __syncthreads();
    }

    float* dst = g_part + (size_t)chunk*524288u;
    int lr = lane >> 2, lc2 = (lane & 3)*2;
    #pragma unroll
    for (int m = 0; m < 2; m++)
        #pragma unroll
        for (int n = 0; n < 2; n++){
            int r0 = wm*32 + m*16 + lr;
            int col = wn*16 + n*8 + lc2;
            float4 d = acc[m*2 + n];
            *(float2*)(dst + (tok0 + r0    )*32 + col) = make_float2(d.x, d.y);
            *(float2*)(dst + (tok0 + r0 + 8)*32 + col) = make_float2(d.z, d.w);
        }
}

// ---------------- out = h + ffp(ff) ----------------
// grid (128, 16): nblk = by>>1, nh = by&1
__global__ __launch_bounds__(256)
void out_k(const float* __restrict__ hin, float* __restrict__ out,
           const float* __restrict__ Wp, const float* __restrict__ Ap){
    extern __shared__ float sm[];
    uint32_t sb = smem_u32(sm);
    int tid = threadIdx.x, warp = tid >> 5, lane = tid & 31;
    int wm = warp >> 1, wn = warp & 1;
    int tile = blockIdx.x, nb2 = blockIdx.y;
    int nblk = nb2 >> 1, nh = nb2 & 1;
    size_t tok0 = (size_t)tile*128;
    int wrow0 = nblk*128 + nh*64;

    float4 acc[8];
    #pragma unroll
    for (int i = 0; i < 8; i++) acc[i] = make_float4(0.f,0.f,0.f,0.f);

    auto fill = [&](int s, int buf){
        uint32_t aB = sb + (uint32_t)buf*24576u;
        uint32_t bB = aB + 16384u;
        if (s < 11){
            stage_tile<1024>(aB, g_ff + tok0*2816 + nblk*352 + (s << 5), 2816);
            stage_tile<512>(bB, Wp + (size_t)wrow0*352 + (s << 5), 352);
        } else {
            stage_tile<1024>(aB, g_Pp + tok0*32, 32);
            stage_tile<512>(bB, Ap + (size_t)wrow0*32, 32);
        }
    };

    fill(0, 0); CPCOMMIT();
    for (int s = 0; s < 12; s++){
        if (s < 11) fill(s + 1, (s + 1) & 1);
        CPCOMMIT(); CPWAIT1(); __syncthreads();
        const float* base = sm + (s & 1)*6144;
        comp_slab<2,4>(base, base + 4096, acc, wm*32, wn*32, lane);
        __syncthreads();
    }

    int lr = lane >> 2, lc2 = (lane & 3)*2;
    #pragma unroll
    for (int m = 0; m < 2; m++)
        #pragma unroll
        for (int n = 0; n < 4; n++){
            int r0 = wm*32 + m*16 + lr;
            int col = wrow0 + wn*32 + n*8 + lc2;
            float4 d = acc[m*4 + n];
            size_t ta = tok0 + r0, tb = ta + 8;
            float2 ha = *(const float2*)(hin + ta*1024 + col);
            float2 hb = *(const float2*)(hin + tb*1024 + col);
            *(float2*)(out + ta*1024 + col) = make_float2(ha.x + d.x, ha.y + d.y);
            *(float2*)(out + tb*1024 + col) = make_float2(hb.x + d.z, hb.y + d.w);
        }
}

// ---------------- launcher ----------------
template <typename T>
static float* symaddr(const T& s){
    void* p = nullptr;
    cudaGetSymbolAddress(&p, s);
    return (float*)p;
}

extern "C" void kernel_launch(void* const* d_in, const int* in_sizes, int n_in,
                              void* d_out, int out_size) {
    const float* x     = (const float*)d_in[0];
    const float* fg_W  = (const float*)d_in[1];
    const float* fg_A  = (const float*)d_in[2];
    const float* fg_B  = (const float*)d_in[3];
    const float* gu_W  = (const float*)d_in[4];
    const float* gu_A  = (const float*)d_in[5];
    const float* gu_B  = (const float*)d_in[6];
    const float* ffg_W = (const float*)d_in[7];
    const float* ffg_A = (const float*)d_in[8];
    const float* ffg_B = (const float*)d_in[9];
    const float* fff_W = (const float*)d_in[10];
    const float* fff_A = (const float*)d_in[11];
    const float* fff_B = (const float*)d_in[12];
    const float* ffp_W = (const float*)d_in[13];
    const float* ffp_A = (const float*)d_in[14];
    const float* ffp_B = (const float*)d_in[15];
    float* out = (float*)d_out;

    float* z    = symaddr(g_z);
    float* h0   = symaddr(g_h0);
    float* h1   = symaddr(g_h1);
    float* P    = symaddr(g_P);
    float* Pp   = symaddr(g_Pp);
    float* part = symaddr(g_part);
    float* wb   = symaddr(g_wb);

    const int SM_P    = 2*6144*4;     // 48 KB
    const int SM_MAIN = 2*8192*4;     // 64 KB
    const int SM_FF   = 2*9728*4;     // 76 KB
    const int SM_PP   = 2*5120*4;     // 40 KB
    const int SM_OUT  = 2*6144*4;     // 48 KB
    cudaFuncSetAttribute(p_k,    cudaFuncAttributeMaxDynamicSharedMemorySize, SM_P);
    cudaFuncSetAttribute(main_k, cudaFuncAttributeMaxDynamicSharedMemorySize, SM_MAIN);
    cudaFuncSetAttribute(ff_k,   cudaFuncAttributeMaxDynamicSharedMemorySize, SM_FF);
    cudaFuncSetAttribute(pp_k,   cudaFuncAttributeMaxDynamicSharedMemorySize, SM_PP);
    cudaFuncSetAttribute(out_k,  cudaFuncAttributeMaxDynamicSharedMemorySize, SM_OUT);

    cvt_k<<<dim3(352, 15), 256>>>(fg_W, gu_W, fg_A, gu_A, fg_B, gu_B,
                                  ffg_W, ffg_A, ffg_B, fff_W, fff_A, fff_B,
                                  ffp_W, ffp_A, ffp_B);

    const float* hcur = x;
    float* bufs[2] = {h0, h1};
    for (int it = 0; it < 4; it++){
        float* hnext = bufs[it & 1];
        rms_k<<<2048, 256>>>(hcur, z);
        p_k<<<dim3(128, 8), 256, SM_P>>>(z, wb + W_FGB, wb + W_GUB, 2, 2048);
        pred_k<<<1024, 256>>>(P, part, 8, (size_t)1048576, 262144);
        main_k<<<dim3(128, 16), 256, SM_MAIN>>>(z, P, hcur, hnext,
                                                wb + W_FGW, wb + W_GUW,
                                                wb + W_FGA, wb + W_GUA);
        hcur = hnext;
    }
    rms_k<<<2048, 256>>>(hcur, z);
    p_k<<<dim3(128, 4), 256, SM_P>>>(z, wb + W_FFGB, wb + W_FFFB, 1, 1024);
    pred_k<<<1024, 256>>>(P, part, 4, (size_t)1048576, 262144);
    ff_k<<<dim3(128, 8, 2), 256, SM_FF>>>(z, P, wb + W_FFGW, wb + W_FFGA, 0, 0);
    ff_k<<<dim3(128, 8, 2), 256, SM_FF>>>(z, P, wb + W_FFFW, wb + W_FFFA, 32, 1);
    pp_k<<<dim3(128, 8), 256, SM_PP>>>(wb + W_FFPB);
    pred_k<<<512, 256>>>(Pp, part, 8, (size_t)524288, 131072);
    out_k<<<dim3(128, 16), 256, SM_OUT>>>(hcur, out, wb + W_FFPW, wb + W_FFPA);
}

// round 9
// speedup vs baseline: 5.3959x; 1.0709x over previous
#include <cuda_runtime.h>
#include <cstdint>
#include <cstddef>

#define EPSRMS 1.1920929e-07f

// ---------------- persistent device scratch ----------------
__device__ float g_z  [16777216];
__device__ float g_h0 [16777216];
__device__ float g_h1 [16777216];
__device__ float g_P  [16384*64];
__device__ float g_Pp [16384*32];
__device__ float g_ffg[16384*2816];
__device__ float g_ff [16384*2816];
__device__ float g_part[8*16384*64];
__device__ float g_wb [2170880];          // tf32-rounded weight copies

// weight offsets inside g_wb
#define W_FGW  0
#define W_GUW  262144
#define W_FGA  524288
#define W_GUA  557056
#define W_FGB  589824
#define W_GUB  655360
#define W_FFGW 720896
#define W_FFGA 1081344
#define W_FFGB 1171456
#define W_FFFW 1204224
#define W_FFFA 1564672
#define W_FFFB 1654784
#define W_FFPW 1687552
#define W_FFPA 2048000
#define W_FFPB 2080768

// ---------------- helpers ----------------
__device__ __forceinline__ float sigm(float x){ return 1.0f/(1.0f+__expf(-x)); }

__device__ __forceinline__ float tf32r(float x){
    uint32_t u;
    asm("cvt.rna.tf32.f32 %0, %1;" : "=r"(u) : "f"(x));
    return __uint_as_float(u);
}

__device__ __forceinline__ uint32_t smem_u32(const void* p){
    uint32_t a;
    asm("{ .reg .u64 t; cvta.to.shared.u64 t, %1; cvt.u32.u64 %0, t; }" : "=r"(a) : "l"(p));
    return a;
}

__device__ __forceinline__ void mma8(float4& d, uint4 a, uint2 b){
    asm volatile(
        "mma.sync.aligned.m16n8k8.row.col.f32.tf32.tf32.f32 "
        "{%0,%1,%2,%3},{%4,%5,%6,%7},{%8,%9},{%0,%1,%2,%3};"
        : "+f"(d.x), "+f"(d.y), "+f"(d.z), "+f"(d.w)
        : "r"(a.x), "r"(a.y), "r"(a.z), "r"(a.w), "r"(b.x), "r"(b.y));
}

__device__ __forceinline__ void ldsm_x4(uint4& r, uint32_t a){
    asm volatile("ldmatrix.sync.aligned.m8n8.x4.shared.b16 {%0,%1,%2,%3}, [%4];"
                 : "=r"(r.x), "=r"(r.y), "=r"(r.z), "=r"(r.w) : "r"(a));
}
__device__ __forceinline__ void ldsm_x2(uint2& r, uint32_t a){
    asm volatile("ldmatrix.sync.aligned.m8n8.x2.shared.b16 {%0,%1}, [%2];"
                 : "=r"(r.x), "=r"(r.y) : "r"(a));
}

__device__ __forceinline__ void cp16(uint32_t dst, const float* src, int sz){
    asm volatile("cp.async.ca.shared.global [%0], [%1], 16, %2;"
                 :: "r"(dst), "l"(src), "r"(sz) : "memory");
}
#define CPCOMMIT() asm volatile("cp.async.commit_group;" ::: "memory")
#define CPWAITG1() asm volatile("cp.async.wait_group 1;"  ::: "memory")

// ---------------- smem staging (row-major, XOR-swizzled 16B chunks) ----------------
// row r, chunk c4(0..7): byte offset = r*128 + ((c4 ^ (r&7))<<4)
template<int NCHUNK>   // NCHUNK = rows*8
__device__ __forceinline__ void stage_tile(uint32_t sb, const float* src, size_t ld){
    int tid = threadIdx.x;
    #pragma unroll
    for (int i = 0; i < (NCHUNK + 255)/256; i++){
        int idx = tid + i*256;
        if ((NCHUNK & 255) && idx >= NCHUNK) continue;
        int r = idx >> 3, c4 = idx & 7;
        cp16(sb + r*128 + ((uint32_t)(c4 ^ (r & 7)) << 4),
             src + (size_t)r*ld + (c4 << 2), 16);
    }
}

// A slab from token rows of z, with causal shift (token = seq0+r-shift; zeros if <0)
__device__ __forceinline__ void stage_tok(uint32_t sb, const float* zb,
                                          int seq0, int shift, int col){
    int tid = threadIdx.x;
    #pragma unroll
    for (int i = 0; i < 4; i++){
        int idx = tid + i*256;
        int r = idx >> 3, c4 = idx & 7;
        int s = seq0 + r - shift;
        int sz = (s >= 0) ? 16 : 0;
        if (s < 0) s = 0;
        cp16(sb + r*128 + ((uint32_t)(c4 ^ (r & 7)) << 4),
             zb + (size_t)s*1024 + col + (c4 << 2), sz);
    }
}

// ---------------- ldmatrix fragment compute over one K=32 slab ----------------
template<int MT, int NT>
__device__ __forceinline__ void compL(uint32_t sAu, uint32_t sBu, float4* acc,
                                      int mb0, int nb0, int lane){
    const int arow = (lane & 7) + ((lane >> 3) & 1) * 8;
    const int khA  = (lane >> 4) & 1;
    uint32_t aB[MT]; int asw[MT];
    #pragma unroll
    for (int m = 0; m < MT; m++){
        int r = mb0 + m*16 + arow;
        aB[m] = sAu + r*128; asw[m] = r & 7;
    }
    constexpr int NP = NT >> 1;
    const int brow = ((lane >> 4) & 1)*8 + (lane & 7);
    const int khB  = (lane >> 3) & 1;
    uint32_t bB[NP > 0 ? NP : 1]; int bsw[NP > 0 ? NP : 1];
    #pragma unroll
    for (int p = 0; p < NP; p++){
        int r = nb0 + p*16 + brow;
        bB[p] = sBu + r*128; bsw[p] = r & 7;
    }
    uint32_t oB = 0; int osw = 0;
    if constexpr (NT & 1){
        int r = nb0 + (NT-1)*8 + (lane & 7);
        oB = sBu + r*128; osw = r & 7;
    }
    #pragma unroll
    for (int kc = 0; kc < 4; kc++){
        uint4 a[MT];
        #pragma unroll
        for (int m = 0; m < MT; m++)
            ldsm_x4(a[m], aB[m] + (uint32_t)((((kc<<1)|khA) ^ asw[m]) << 4));
        #pragma unroll
        for (int p = 0; p < NP; p++){
            uint4 b;
            ldsm_x4(b, bB[p] + (uint32_t)((((kc<<1)|khB) ^ bsw[p]) << 4));
            #pragma unroll
            for (int m = 0; m < MT; m++){
                mma8(acc[m*NT + 2*p    ], a[m], make_uint2(b.x, b.y));
                mma8(acc[m*NT + 2*p + 1], a[m], make_uint2(b.z, b.w));
            }
        }
        if constexpr (NT & 1){
            uint2 b;
            ldsm_x2(b, oB + (uint32_t)((((kc<<1)|khB) ^ osw) << 4));
            #pragma unroll
            for (int m = 0; m < MT; m++)
                mma8(acc[m*NT + NT - 1], a[m], b);
        }
    }
}

// dual-B variant (shares A fragments)
template<int MT, int NT>
__device__ __forceinline__ void compL2(uint32_t sAu, uint32_t sB1, uint32_t sB2,
                                       float4* acc1, float4* acc2,
                                       int mb0, int nb0, int lane){
    static_assert((NT & 1) == 0, "NT even");
    const int arow = (lane & 7) + ((lane >> 3) & 1) * 8;
    const int khA  = (lane >> 4) & 1;
    uint32_t aB[MT]; int asw[MT];
    #pragma unroll
    for (int m = 0; m < MT; m++){
        int r = mb0 + m*16 + arow;
        aB[m] = sAu + r*128; asw[m] = r & 7;
    }
    constexpr int NP = NT >> 1;
    const int brow = ((lane >> 4) & 1)*8 + (lane & 7);
    const int khB  = (lane >> 3) & 1;
    uint32_t b1B[NP], b2B[NP]; int bsw[NP];
    #pragma unroll
    for (int p = 0; p < NP; p++){
        int r = nb0 + p*16 + brow;
        b1B[p] = sB1 + r*128; b2B[p] = sB2 + r*128; bsw[p] = r & 7;
    }
    #pragma unroll
    for (int kc = 0; kc < 4; kc++){
        uint4 a[MT];
        #pragma unroll
        for (int m = 0; m < MT; m++)
            ldsm_x4(a[m], aB[m] + (uint32_t)((((kc<<1)|khA) ^ asw[m]) << 4));
        #pragma unroll
        for (int p = 0; p < NP; p++){
            uint32_t off = (uint32_t)((((kc<<1)|khB) ^ bsw[p]) << 4);
            uint4 b1, b2;
            ldsm_x4(b1, b1B[p] + off);
            ldsm_x4(b2, b2B[p] + off);
            #pragma unroll
            for (int m = 0; m < MT; m++){
                mma8(acc1[m*NT + 2*p    ], a[m], make_uint2(b1.x, b1.y));
                mma8(acc1[m*NT + 2*p + 1], a[m], make_uint2(b1.z, b1.w));
                mma8(acc2[m*NT + 2*p    ], a[m], make_uint2(b2.x, b2.y));
                mma8(acc2[m*NT + 2*p + 1], a[m], make_uint2(b2.z, b2.w));
            }
        }
    }
}

// ---------------- weight tf32 pre-rounding ----------------
__global__ void cvt_k(const float* p0, const float* p1, const float* p2, const float* p3,
                      const float* p4, const float* p5, const float* p6, const float* p7,
                      const float* p8, const float* p9, const float* p10, const float* p11,
                      const float* p12, const float* p13, const float* p14){
    const float* srcs[15] = {p0,p1,p2,p3,p4,p5,p6,p7,p8,p9,p10,p11,p12,p13,p14};
    const int sz4[15] = {65536,65536,8192,8192,16384,16384,90112,22528,8192,
                         90112,22528,8192,90112,8192,22528};
    const int off[15] = {W_FGW,W_GUW,W_FGA,W_GUA,W_FGB,W_GUB,W_FFGW,W_FFGA,W_FFGB,
                         W_FFFW,W_FFFA,W_FFFB,W_FFPW,W_FFPA,W_FFPB};
    int t = blockIdx.y;
    int i = blockIdx.x*256 + threadIdx.x;
    if (i >= sz4[t]) return;
    float4 v = ((const float4*)srcs[t])[i];
    v.x = tf32r(v.x); v.y = tf32r(v.y); v.z = tf32r(v.z); v.w = tf32r(v.w);
    ((float4*)(g_wb + off[t]))[i] = v;
}

// ---------------- rmsnorm: h -> z (tf32-rounded output) ----------------
__global__ __launch_bounds__(256)
void rms_k(const float* __restrict__ h, float* __restrict__ z){
    int warp = threadIdx.x >> 5, lane = threadIdx.x & 31;
    size_t tok = (size_t)blockIdx.x*8 + warp;
    const float4* hr = (const float4*)(h + tok*1024);
    float4 v[8]; float ss = 0.f;
    #pragma unroll
    for (int j = 0; j < 8; j++){
        v[j] = hr[lane + 32*j];
        ss += v[j].x*v[j].x + v[j].y*v[j].y + v[j].z*v[j].z + v[j].w*v[j].w;
    }
    #pragma unroll
    for (int o = 16; o; o >>= 1) ss += __shfl_xor_sync(0xffffffffu, ss, o);
    float sc = rsqrtf(ss*(1.f/1024.f) + EPSRMS);
    float4* zr = (float4*)(z + tok*1024);
    #pragma unroll
    for (int j = 0; j < 8; j++){
        float4 w;
        w.x = tf32r(v[j].x*sc); w.y = tf32r(v[j].y*sc);
        w.z = tf32r(v[j].z*sc); w.w = tf32r(v[j].w*sc);
        zr[lane + 32*j] = w;
    }
}

// ---------------- low-rank projection partials ----------------
__global__ __launch_bounds__(256)
void p_k(const float* __restrict__ z, const float* __restrict__ B1,
         const float* __restrict__ B2, int halves, int ldB){
    extern __shared__ float sm[];
    uint32_t sb = smem_u32(sm);
    int tid = threadIdx.x, warp = tid >> 5, lane = tid & 31;
    int wm = warp >> 1, wn = warp & 1;
    int tile = blockIdx.x, chunk = blockIdx.y;
    int batch = tile >> 4, seq0 = (tile & 15) << 7;
    const float* zb = z + (size_t)batch*2048*1024;
    int half = (halves == 2) ? (chunk >> 2) : 0;
    int colbase = ((halves == 2) ? (chunk & 3) : chunk) << 8;
    int koff = half*1024 + colbase;

    float4 acc[8];
    #pragma unroll
    for (int i = 0; i < 8; i++) acc[i] = make_float4(0.f,0.f,0.f,0.f);

    auto fill = [&](int s, int buf){
        uint32_t aB = sb + (uint32_t)buf*24576u;
        uint32_t bB = aB + 16384u;
        stage_tok(aB, zb, seq0, half, colbase + (s << 5));
        int ko = koff + (s << 5);
        #pragma unroll
        for (int i = 0; i < 2; i++){
            int idx = tid + i*256;
            int r = idx >> 3, c4 = idx & 7;
            const float* src = ((r < 32) ? B1 : B2) + (size_t)(r & 31)*ldB + ko + (c4 << 2);
            cp16(bB + r*128 + ((uint32_t)(c4 ^ (r & 7)) << 4), src, 16);
        }
    };

    fill(0, 0); CPCOMMIT();
    fill(1, 1); CPCOMMIT();
    for (int s = 0; s < 8; s++){
        CPWAITG1(); __syncthreads();
        uint32_t aB = sb + (uint32_t)(s % 3)*24576u;
        compL<2,4>(aB, aB + 16384u, acc, wm*32, wn*32, lane);
        if (s + 2 < 8) fill(s + 2, (s + 2) % 3);
        CPCOMMIT();
    }

    size_t tok0 = (size_t)tile*128;
    float* dst = g_part + (size_t)chunk*1048576u;
    int lr = lane >> 2, lc2 = (lane & 3)*2;
    #pragma unroll
    for (int m = 0; m < 2; m++)
        #pragma unroll
        for (int n = 0; n < 4; n++){
            int r0 = wm*32 + m*16 + lr;
            int col = wn*32 + n*8 + lc2;
            float4 d = acc[m*4 + n];
            *(float2*)(dst + (tok0 + r0    )*64 + col) = make_float2(d.x, d.y);
            *(float2*)(dst + (tok0 + r0 + 8)*64 + col) = make_float2(d.z, d.w);
        }
}

// reduce partials (+ tf32 round)
__global__ void pred_k(float* __restrict__ dst, const float* __restrict__ src,
                       int nch, size_t cstride, int n4){
    int i = blockIdx.x*256 + threadIdx.x;
    if (i >= n4) return;
    float4 a = ((const float4*)src)[i];
    for (int c = 1; c < nch; c++){
        float4 v = ((const float4*)(src + (size_t)c*cstride))[i];
        a.x += v.x; a.y += v.y; a.z += v.z; a.w += v.w;
    }
    a.x = tf32r(a.x); a.y = tf32r(a.y); a.z = tf32r(a.z); a.w = tf32r(a.w);
    ((float4*)dst)[i] = a;
}

// ---------------- iteration main GEMM ----------------
__global__ __launch_bounds__(256)
void main_k(const float* __restrict__ z, const float* __restrict__ P,
            const float* __restrict__ hin, float* __restrict__ hout,
            const float* __restrict__ Wg, const float* __restrict__ Wu,
            const float* __restrict__ Ag, const float* __restrict__ Au){
    extern __shared__ float sm[];
    uint32_t sb = smem_u32(sm);
    int tid = threadIdx.x, warp = tid >> 5, lane = tid & 31;
    int wm = warp >> 1, wn = warp & 1;
    int tile = blockIdx.x, nb2 = blockIdx.y;
    int nblk = nb2 >> 1, nh = nb2 & 1;
    int batch = tile >> 4, seq0 = (tile & 15) << 7;
    const float* zb = z + (size_t)batch*2048*1024;
    int shift = (nblk >= 4) ? 1 : 0;
    int colbase0 = (nblk & 3) << 8;
    size_t tok0 = (size_t)tile*128;
    int wrow0 = nblk*128 + nh*64;

    float4 accg[8], accu[8];
    #pragma unroll
    for (int i = 0; i < 8; i++){
        accg[i] = make_float4(0.f,0.f,0.f,0.f);
        accu[i] = make_float4(0.f,0.f,0.f,0.f);
    }

    auto fill = [&](int s, int buf){
        uint32_t aB = sb + (uint32_t)buf*32768u;
        uint32_t gB = aB + 16384u, uB = aB + 24576u;
        if (s < 8){
            stage_tok(aB, zb, seq0, shift, colbase0 + (s << 5));
            const float* g = Wg + (size_t)wrow0*256 + (s << 5);
            const float* u = Wu + (size_t)wrow0*256 + (s << 5);
            #pragma unroll
            for (int i = 0; i < 2; i++){
                int idx = tid + i*256;
                int r = idx >> 3, c4 = idx & 7;
                uint32_t so = r*128 + ((uint32_t)(c4 ^ (r & 7)) << 4);
                cp16(gB + so, g + (size_t)r*256 + (c4 << 2), 16);
                cp16(uB + so, u + (size_t)r*256 + (c4 << 2), 16);
            }
        } else {
            int isg = (s == 8);
            stage_tile<1024>(aB, P + tok0*64 + (isg ? 0 : 32), 64);
            stage_tile<512>(isg ? gB : uB,
                            (isg ? Ag : Au) + (size_t)wrow0*32, 32);
        }
    };

    fill(0, 0); CPCOMMIT();
    fill(1, 1); CPCOMMIT();
    for (int s = 0; s < 10; s++){
        CPWAITG1(); __syncthreads();
        uint32_t aB = sb + (uint32_t)(s % 3)*32768u;
        uint32_t gB = aB + 16384u, uB = aB + 24576u;
        if (s < 8)
            compL2<2,4>(aB, gB, uB, accg, accu, wm*32, wn*32, lane);
        else if (s == 8)
            compL<2,4>(aB, gB, accg, wm*32, wn*32, lane);
        else
            compL<2,4>(aB, uB, accu, wm*32, wn*32, lane);
        if (s + 2 < 10) fill(s + 2, (s + 2) % 3);
        CPCOMMIT();
    }

    int lr = lane >> 2, lc2 = (lane & 3)*2;
    #pragma unroll
    for (int m = 0; m < 2; m++)
        #pragma unroll
        for (int n = 0; n < 4; n++){
            int r0 = wm*32 + m*16 + lr;
            int col = wrow0 + wn*32 + n*8 + lc2;
            float4 dg = accg[m*4 + n], du = accu[m*4 + n];
            size_t ta = tok0 + r0, tb = ta + 8;
            float2 ha = *(const float2*)(hin + ta*1024 + col);
            float2 hb = *(const float2*)(hin + tb*1024 + col);
            float2 oa, ob;
            oa.x = fmaf(sigm(dg.x), du.x, ha.x);
            oa.y = fmaf(sigm(dg.y), du.y, ha.y);
            ob.x = fmaf(sigm(dg.z), du.z, hb.x);
            ob.y = fmaf(sigm(dg.w), du.w, hb.y);
            *(float2*)(hout + ta*1024 + col) = oa;
            *(float2*)(hout + tb*1024 + col) = ob;
        }
}

// ---------------- ff GEMM (mode0: raw ffg; mode1: silu(ffg)*fff -> g_ff) ----------------
__global__ __launch_bounds__(256)
void ff_k(const float* __restrict__ z, const float* __restrict__ P,
          const float* __restrict__ W, const float* __restrict__ Alr,
          int pofs, int mode){
    extern __shared__ float sm[];
    uint32_t sb = smem_u32(sm);
    int tid = threadIdx.x, warp = tid >> 5, lane = tid & 31;
    int wm = warp >> 1, wn = warp & 1;
    int tile = blockIdx.x, nblk = blockIdx.y, nsub = blockIdx.z;
    int n0 = nblk*352 + nsub*176;
    size_t tok0 = (size_t)tile*128;

    float4 acc[22];
    #pragma unroll
    for (int i = 0; i < 22; i++) acc[i] = make_float4(0.f,0.f,0.f,0.f);

    auto fill = [&](int s, int buf){
        uint32_t aB = sb + (uint32_t)buf*38912u;
        uint32_t bB = aB + 16384u;
        if (s < 4){
            stage_tile<1024>(aB, z + tok0*1024 + nblk*128 + (s << 5), 1024);
            stage_tile<1408>(bB, W + (size_t)n0*128 + (s << 5), 128);
        } else {
            stage_tile<1024>(aB, P + tok0*64 + pofs, 64);
            stage_tile<1408>(bB, Alr + (size_t)n0*32, 32);
        }
    };

    fill(0, 0); CPCOMMIT();
    fill(1, 1); CPCOMMIT();
    for (int s = 0; s < 5; s++){
        CPWAITG1(); __syncthreads();
        uint32_t aB = sb + (uint32_t)(s % 3)*38912u;
        compL<2,11>(aB, aB + 16384u, acc, wm*32, wn*88, lane);
        if (s + 2 < 5) fill(s + 2, (s + 2) % 3);
        CPCOMMIT();
    }

    int lr = lane >> 2, lc2 = (lane & 3)*2;
    #pragma unroll
    for (int m = 0; m < 2; m++)
        #pragma unroll
        for (int n = 0; n < 11; n++){
            int r0 = wm*32 + m*16 + lr;
            int col = n0 + wn*88 + n*8 + lc2;
            float4 d = acc[m*11 + n];
            size_t ia = (tok0 + r0)*2816 + col;
            size_t ib = (tok0 + r0 + 8)*2816 + col;
            if (mode == 0){
                *(float2*)(g_ffg + ia) = make_float2(d.x, d.y);
                *(float2*)(g_ffg + ib) = make_float2(d.z, d.w);
            } else {
                float2 ga = *(const float2*)(g_ffg + ia);
                float2 gb = *(const float2*)(g_ffg + ib);
                float2 oa, ob;
                oa.x = tf32r(ga.x*sigm(ga.x)*d.x);
                oa.y = tf32r(ga.y*sigm(ga.y)*d.y);
                ob.x = tf32r(gb.x*sigm(gb.x)*d.z);
                ob.y = tf32r(gb.y*sigm(gb.y)*d.w);
                *(float2*)(g_ff + ia) = oa;
                *(float2*)(g_ff + ib) = ob;
            }
        }
}

// ---------------- Pp partials: ff . ffp_B^T, K-split 8 x 352 ----------------
__global__ __launch_bounds__(256)
void pp_k(const float* __restrict__ ffpB){
    extern __shared__ float sm[];
    uint32_t sb = smem_u32(sm);
    int tid = threadIdx.x, warp = tid >> 5, lane = tid & 31;
    int wm = warp >> 1, wn = warp & 1;
    int tile = blockIdx.x, chunk = blockIdx.y;
    size_t tok0 = (size_t)tile*128;

    float4 acc[4];
    #pragma unroll
    for (int i = 0; i < 4; i++) acc[i] = make_float4(0.f,0.f,0.f,0.f);

    auto fill = [&](int s, int buf){
        uint32_t aB = sb + (uint32_t)buf*20480u;
        uint32_t bB = aB + 16384u;
        stage_tile<1024>(aB, g_ff + tok0*2816 + chunk*352 + (s << 5), 2816);
        stage_tile<256>(bB, ffpB + chunk*352 + (s << 5), 2816);
    };

    fill(0, 0); CPCOMMIT();
    fill(1, 1); CPCOMMIT();
    for (int s = 0; s < 11; s++){
        CPWAITG1(); __syncthreads();
        uint32_t aB = sb + (uint32_t)(s % 3)*20480u;
        compL<2,2>(aB, aB + 16384u, acc, wm*32, wn*16, lane);
        if (s + 2 < 11) fill(s + 2, (s + 2) % 3);
        CPCOMMIT();
    }

    float* dst = g_part + (size_t)chunk*524288u;
    int lr = lane >> 2, lc2 = (lane & 3)*2;
    #pragma unroll
    for (int m = 0; m < 2; m++)
        #pragma unroll
        for (int n = 0; n < 2; n++){
            int r0 = wm*32 + m*16 + lr;
            int col = wn*16 + n*8 + lc2;
            float4 d = acc[m*2 + n];
            *(float2*)(dst + (tok0 + r0    )*32 + col) = make_float2(d.x, d.y);
            *(float2*)(dst + (tok0 + r0 + 8)*32 + col) = make_float2(d.z, d.w);
        }
}

// ---------------- out = h + ffp(ff) ----------------
__global__ __launch_bounds__(256)
void out_k(const float* __restrict__ hin, float* __restrict__ out,
           const float* __restrict__ Wp, const float* __restrict__ Ap){
    extern __shared__ float sm[];
    uint32_t sb = smem_u32(sm);
    int tid = threadIdx.x, warp = tid >> 5, lane = tid & 31;
    int wm = warp >> 1, wn = warp & 1;
    int tile = blockIdx.x, nb2 = blockIdx.y;
    int nblk = nb2 >> 1, nh = nb2 & 1;
    size_t tok0 = (size_t)tile*128;
    int wrow0 = nblk*128 + nh*64;

    float4 acc[8];
    #pragma unroll
    for (int i = 0; i < 8; i++) acc[i] = make_float4(0.f,0.f,0.f,0.f);

    auto fill = [&](int s, int buf){
        uint32_t aB = sb + (uint32_t)buf*24576u;
        uint32_t bB = aB + 16384u;
        if (s < 11){
            stage_tile<1024>(aB, g_ff + tok0*2816 + nblk*352 + (s << 5), 2816);
            stage_tile<512>(bB, Wp + (size_t)wrow0*352 + (s << 5), 352);
        } else {
            stage_tile<1024>(aB, g_Pp + tok0*32, 32);
            stage_tile<512>(bB, Ap + (size_t)wrow0*32, 32);
        }
    };

    fill(0, 0); CPCOMMIT();
    fill(1, 1); CPCOMMIT();
    for (int s = 0; s < 12; s++){
        CPWAITG1(); __syncthreads();
        uint32_t aB = sb + (uint32_t)(s % 3)*24576u;
        compL<2,4>(aB, aB + 16384u, acc, wm*32, wn*32, lane);
        if (s + 2 < 12) fill(s + 2, (s + 2) % 3);
        CPCOMMIT();
    }

    int lr = lane >> 2, lc2 = (lane & 3)*2;
    #pragma unroll
    for (int m = 0; m < 2; m++)
        #pragma unroll
        for (int n = 0; n < 4; n++){
            int r0 = wm*32 + m*16 + lr;
            int col = wrow0 + wn*32 + n*8 + lc2;
            float4 d = acc[m*4 + n];
            size_t ta = tok0 + r0, tb = ta + 8;
            float2 ha = *(const float2*)(hin + ta*1024 + col);
            float2 hb = *(const float2*)(hin + tb*1024 + col);
            *(float2*)(out + ta*1024 + col) = make_float2(ha.x + d.x, ha.y + d.y);
            *(float2*)(out + tb*1024 + col) = make_float2(hb.x + d.z, hb.y + d.w);
        }
}

// ---------------- launcher ----------------
template <typename T>
static float* symaddr(const T& s){
    void* p = nullptr;
    cudaGetSymbolAddress(&p, s);
    return (float*)p;
}

extern "C" void kernel_launch(void* const* d_in, const int* in_sizes, int n_in,
                              void* d_out, int out_size) {
    const float* x     = (const float*)d_in[0];
    const float* fg_W  = (const float*)d_in[1];
    const float* fg_A  = (const float*)d_in[2];
    const float* fg_B  = (const float*)d_in[3];
    const float* gu_W  = (const float*)d_in[4];
    const float* gu_A  = (const float*)d_in[5];
    const float* gu_B  = (const float*)d_in[6];
    const float* ffg_W = (const float*)d_in[7];
    const float* ffg_A = (const float*)d_in[8];
    const float* ffg_B = (const float*)d_in[9];
    const float* fff_W = (const float*)d_in[10];
    const float* fff_A = (const float*)d_in[11];
    const float* fff_B = (const float*)d_in[12];
    const float* ffp_W = (const float*)d_in[13];
    const float* ffp_A = (const float*)d_in[14];
    const float* ffp_B = (const float*)d_in[15];
    float* out = (float*)d_out;

    float* z    = symaddr(g_z);
    float* h0   = symaddr(g_h0);
    float* h1   = symaddr(g_h1);
    float* P    = symaddr(g_P);
    float* Pp   = symaddr(g_Pp);
    float* part = symaddr(g_part);
    float* wb   = symaddr(g_wb);

    const int SM_P    = 3*24576;
    const int SM_MAIN = 3*32768;
    const int SM_FF   = 3*38912;
    const int SM_PP   = 3*20480;
    const int SM_OUT  = 3*24576;
    cudaFuncSetAttribute(p_k,    cudaFuncAttributeMaxDynamicSharedMemorySize, SM_P);
    cudaFuncSetAttribute(main_k, cudaFuncAttributeMaxDynamicSharedMemorySize, SM_MAIN);
    cudaFuncSetAttribute(ff_k,   cudaFuncAttributeMaxDynamicSharedMemorySize, SM_FF);
    cudaFuncSetAttribute(pp_k,   cudaFuncAttributeMaxDynamicSharedMemorySize, SM_PP);
    cudaFuncSetAttribute(out_k,  cudaFuncAttributeMaxDynamicSharedMemorySize, SM_OUT);

    cvt_k<<<dim3(352, 15), 256>>>(fg_W, gu_W, fg_A, gu_A, fg_B, gu_B,
                                  ffg_W, ffg_A, ffg_B, fff_W, fff_A, fff_B,
                                  ffp_W, ffp_A, ffp_B);

    const float* hcur = x;
    float* bufs[2] = {h0, h1};
    for (int it = 0; it < 4; it++){
        float* hnext = bufs[it & 1];
        rms_k<<<2048, 256>>>(hcur, z);
        p_k<<<dim3(128, 8), 256, SM_P>>>(z, wb + W_FGB, wb + W_GUB, 2, 2048);
        pred_k<<<1024, 256>>>(P, part, 8, (size_t)1048576, 262144);
        main_k<<<dim3(128, 16), 256, SM_MAIN>>>(z, P, hcur, hnext,
                                                wb + W_FGW, wb + W_GUW,
                                                wb + W_FGA, wb + W_GUA);
        hcur = hnext;
    }
    rms_k<<<2048, 256>>>(hcur, z);
    p_k<<<dim3(128, 4), 256, SM_P>>>(z, wb + W_FFGB, wb + W_FFFB, 1, 1024);
    pred_k<<<1024, 256>>>(P, part, 4, (size_t)1048576, 262144);
    ff_k<<<dim3(128, 8, 2), 256, SM_FF>>>(z, P, wb + W_FFGW, wb + W_FFGA, 0, 0);
    ff_k<<<dim3(128, 8, 2), 256, SM_FF>>>(z, P, wb + W_FFFW, wb + W_FFFA, 32, 1);
    pp_k<<<dim3(128, 8), 256, SM_PP>>>(wb + W_FFPB);
    pred_k<<<512, 256>>>(Pp, part, 8, (size_t)524288, 131072);
    out_k<<<dim3(128, 16), 256, SM_OUT>>>(hcur, out, wb + W_FFPW, wb + W_FFPA);
}

// round 10
// speedup vs baseline: 8.0938x; 1.5000x over previous
#include <cuda_runtime.h>
#include <cuda_fp16.h>
#include <cstdint>
#include <cstddef>

#define EPSRMS 1.1920929e-07f

// ---------------- persistent device scratch ----------------
__device__ __half g_z [16777216];          // rmsnorm output (fp16)
__device__ float  g_h0[16777216];
__device__ float  g_h1[16777216];
__device__ __half g_P [16384*64];
__device__ __half g_Pp[16384*32];
__device__ __half g_ff[16384*2816];        // silu(ffg)*fff (fp16)
__device__ float  g_part[8*16384*64];
__device__ __half g_wh[2170880];           // fp16 weight copies

// weight offsets inside g_wh (element counts)
#define W_FGW  0
#define W_GUW  262144
#define W_FGA  524288
#define W_GUA  557056
#define W_FGB  589824
#define W_GUB  655360
#define W_FFGW 720896
#define W_FFGA 1081344
#define W_FFGB 1171456
#define W_FFFW 1204224
#define W_FFFA 1564672
#define W_FFFB 1654784
#define W_FFPW 1687552
#define W_FFPA 2048000
#define W_FFPB 2080768

// ---------------- helpers ----------------
__device__ __forceinline__ float sigm(float x){ return 1.0f/(1.0f+__expf(-x)); }

__device__ __forceinline__ uint32_t smem_u32(const void* p){
    uint32_t a;
    asm("{ .reg .u64 t; cvta.to.shared.u64 t, %1; cvt.u32.u64 %0, t; }" : "=r"(a) : "l"(p));
    return a;
}

__device__ __forceinline__ void mma16(float4& d, uint4 a, uint2 b){
    asm volatile(
        "mma.sync.aligned.m16n8k16.row.col.f32.f16.f16.f32 "
        "{%0,%1,%2,%3},{%4,%5,%6,%7},{%8,%9},{%0,%1,%2,%3};"
        : "+f"(d.x), "+f"(d.y), "+f"(d.z), "+f"(d.w)
        : "r"(a.x), "r"(a.y), "r"(a.z), "r"(a.w), "r"(b.x), "r"(b.y));
}

__device__ __forceinline__ void ldsm_x4(uint4& r, uint32_t a){
    asm volatile("ldmatrix.sync.aligned.m8n8.x4.shared.b16 {%0,%1,%2,%3}, [%4];"
                 : "=r"(r.x), "=r"(r.y), "=r"(r.z), "=r"(r.w) : "r"(a));
}
__device__ __forceinline__ void ldsm_x2(uint2& r, uint32_t a){
    asm volatile("ldmatrix.sync.aligned.m8n8.x2.shared.b16 {%0,%1}, [%2];"
                 : "=r"(r.x), "=r"(r.y) : "r"(a));
}

__device__ __forceinline__ void cp16(uint32_t dst, const void* src, int sz){
    asm volatile("cp.async.ca.shared.global [%0], [%1], 16, %2;"
                 :: "r"(dst), "l"(src), "r"(sz) : "memory");
}
#define CPCOMMIT() asm volatile("cp.async.commit_group;" ::: "memory")
#define CPWAITG1() asm volatile("cp.async.wait_group 1;"  ::: "memory")

// ---------------- smem staging (rows of 128B = 64 fp16, XOR-swizzled 16B chunks) ----------
// row r, chunk c4(0..7): byte offset = r*128 + ((c4 ^ (r&7))<<4)
template<int NCHUNK>   // NCHUNK = rows*8
__device__ __forceinline__ void stage_tile(uint32_t sb, const __half* src, size_t ld){
    int tid = threadIdx.x;
    #pragma unroll
    for (int i = 0; i < (NCHUNK + 255)/256; i++){
        int idx = tid + i*256;
        if ((NCHUNK & 255) && idx >= NCHUNK) continue;
        int r = idx >> 3, c4 = idx & 7;
        cp16(sb + r*128 + ((uint32_t)(c4 ^ (r & 7)) << 4),
             src + (size_t)r*ld + (c4 << 3), 16);
    }
}

// staging with only vc valid chunks per row (rest zero-filled)
template<int NCHUNK>
__device__ __forceinline__ void stage_tile_vc(uint32_t sb, const __half* src, size_t ld, int vc){
    int tid = threadIdx.x;
    #pragma unroll
    for (int i = 0; i < (NCHUNK + 255)/256; i++){
        int idx = tid + i*256;
        if ((NCHUNK & 255) && idx >= NCHUNK) continue;
        int r = idx >> 3, c4 = idx & 7;
        int ok = (c4 < vc);
        cp16(sb + r*128 + ((uint32_t)(c4 ^ (r & 7)) << 4),
             src + (size_t)r*ld + ((ok ? c4 : 0) << 3), ok ? 16 : 0);
    }
}

// A slab from token rows of z (fp16), causal shift (token = seq0+r-shift; zeros if <0)
__device__ __forceinline__ void stage_tok(uint32_t sb, const __half* zb,
                                          int seq0, int shift, int col){
    int tid = threadIdx.x;
    #pragma unroll
    for (int i = 0; i < 4; i++){
        int idx = tid + i*256;
        int r = idx >> 3, c4 = idx & 7;
        int s = seq0 + r - shift;
        int sz = (s >= 0) ? 16 : 0;
        if (s < 0) s = 0;
        cp16(sb + r*128 + ((uint32_t)(c4 ^ (r & 7)) << 4),
             zb + (size_t)s*1024 + col + (c4 << 3), sz);
    }
}

// ---------------- fp16 ldmatrix fragment compute over one K=64 slab ----------------
// A frag m16k16 via ldsm.x4: lanes 0-7 m0-7/klo, 8-15 m8-15/klo, 16-23 m0-7/khi, 24-31 m8-15/khi
// B pair (two n-tiles) via ldsm.x4: lanes 0-7 np/klo, 8-15 np/khi, 16-23 np+1/klo, 24-31 np+1/khi
template<int MT, int NT>
__device__ __forceinline__ void compLh(uint32_t sAu, uint32_t sBu, float4* acc,
                                       int mb0, int nb0, int lane){
    const int arow = (lane & 7) + ((lane >> 3) & 1)*8;
    const int khA  = (lane >> 4) & 1;
    uint32_t aB[MT]; int asw[MT];
    #pragma unroll
    for (int m = 0; m < MT; m++){
        int r = mb0 + m*16 + arow;
        aB[m] = sAu + r*128; asw[m] = r & 7;
    }
    constexpr int NP = NT >> 1;
    const int brow = ((lane >> 4) & 1)*8 + (lane & 7);
    const int khB  = (lane >> 3) & 1;
    uint32_t bB[NP > 0 ? NP : 1]; int bsw[NP > 0 ? NP : 1];
    #pragma unroll
    for (int p = 0; p < NP; p++){
        int r = nb0 + p*16 + brow;
        bB[p] = sBu + r*128; bsw[p] = r & 7;
    }
    uint32_t oB = 0; int osw = 0;
    if constexpr (NT & 1){
        int r = nb0 + (NT-1)*8 + (lane & 7);
        oB = sBu + r*128; osw = r & 7;
    }
    const int khO = (lane >> 3) & 1;
    #pragma unroll
    for (int kc = 0; kc < 4; kc++){
        uint4 a[MT];
        #pragma unroll
        for (int m = 0; m < MT; m++)
            ldsm_x4(a[m], aB[m] + (uint32_t)((((kc<<1)|khA) ^ asw[m]) << 4));
        #pragma unroll
        for (int p = 0; p < NP; p++){
            uint4 b;
            ldsm_x4(b, bB[p] + (uint32_t)((((kc<<1)|khB) ^ bsw[p]) << 4));
            #pragma unroll
            for (int m = 0; m < MT; m++){
                mma16(acc[m*NT + 2*p    ], a[m], make_uint2(b.x, b.y));
                mma16(acc[m*NT + 2*p + 1], a[m], make_uint2(b.z, b.w));
            }
        }
        if constexpr (NT & 1){
            uint2 b;
            ldsm_x2(b, oB + (uint32_t)((((kc<<1)|khO) ^ osw) << 4));
            #pragma unroll
            for (int m = 0; m < MT; m++)
                mma16(acc[m*NT + NT - 1], a[m], b);
        }
    }
}

// dual-B variant (shares A fragments)
template<int MT, int NT>
__device__ __forceinline__ void compL2h(uint32_t sAu, uint32_t sB1, uint32_t sB2,
                                        float4* acc1, float4* acc2,
                                        int mb0, int nb0, int lane){
    static_assert((NT & 1) == 0, "NT even");
    const int arow = (lane & 7) + ((lane >> 3) & 1)*8;
    const int khA  = (lane >> 4) & 1;
    uint32_t aB[MT]; int asw[MT];
    #pragma unroll
    for (int m = 0; m < MT; m++){
        int r = mb0 + m*16 + arow;
        aB[m] = sAu + r*128; asw[m] = r & 7;
    }
    constexpr int NP = NT >> 1;
    const int brow = ((lane >> 4) & 1)*8 + (lane & 7);
    const int khB  = (lane >> 3) & 1;
    uint32_t b1B[NP], b2B[NP]; int bsw[NP];
    #pragma unroll
    for (int p = 0; p < NP; p++){
        int r = nb0 + p*16 + brow;
        b1B[p] = sB1 + r*128; b2B[p] = sB2 + r*128; bsw[p] = r & 7;
    }
    #pragma unroll
    for (int kc = 0; kc < 4; kc++){
        uint4 a[MT];
        #pragma unroll
        for (int m = 0; m < MT; m++)
            ldsm_x4(a[m], aB[m] + (uint32_t)((((kc<<1)|khA) ^ asw[m]) << 4));
        #pragma unroll
        for (int p = 0; p < NP; p++){
            uint32_t off = (uint32_t)((((kc<<1)|khB) ^ bsw[p]) << 4);
            uint4 b1, b2;
            ldsm_x4(b1, b1B[p] + off);
            ldsm_x4(b2, b2B[p] + off);
            #pragma unroll
            for (int m = 0; m < MT; m++){
                mma16(acc1[m*NT + 2*p    ], a[m], make_uint2(b1.x, b1.y));
                mma16(acc1[m*NT + 2*p + 1], a[m], make_uint2(b1.z, b1.w));
                mma16(acc2[m*NT + 2*p    ], a[m], make_uint2(b2.x, b2.y));
                mma16(acc2[m*NT + 2*p + 1], a[m], make_uint2(b2.z, b2.w));
            }
        }
    }
}

// ---------------- weight fp16 conversion ----------------
__global__ void cvt_k(const float* p0, const float* p1, const float* p2, const float* p3,
                      const float* p4, const float* p5, const float* p6, const float* p7,
                      const float* p8, const float* p9, const float* p10, const float* p11,
                      const float* p12, const float* p13, const float* p14){
    const float* srcs[15] = {p0,p1,p2,p3,p4,p5,p6,p7,p8,p9,p10,p11,p12,p13,p14};
    const int sz4[15] = {65536,65536,8192,8192,16384,16384,90112,22528,8192,
                         90112,22528,8192,90112,8192,22528};
    const int off[15] = {W_FGW,W_GUW,W_FGA,W_GUA,W_FGB,W_GUB,W_FFGW,W_FFGA,W_FFGB,
                         W_FFFW,W_FFFA,W_FFFB,W_FFPW,W_FFPA,W_FFPB};
    int t = blockIdx.y;
    int i = blockIdx.x*256 + threadIdx.x;
    if (i >= sz4[t]) return;
    float4 v = ((const float4*)srcs[t])[i];
    __half2* dst = (__half2*)(g_wh + off[t]);
    dst[2*i]     = __floats2half2_rn(v.x, v.y);
    dst[2*i + 1] = __floats2half2_rn(v.z, v.w);
}

// ---------------- rmsnorm: h -> z (fp16 output) ----------------
__global__ __launch_bounds__(256)
void rms_k(const float* __restrict__ h, __half* __restrict__ z){
    int warp = threadIdx.x >> 5, lane = threadIdx.x & 31;
    size_t tok = (size_t)blockIdx.x*8 + warp;
    const float4* hr = (const float4*)(h + tok*1024);
    float4 v[8]; float ss = 0.f;
    #pragma unroll
    for (int j = 0; j < 8; j++){
        v[j] = hr[lane + 32*j];
        ss += v[j].x*v[j].x + v[j].y*v[j].y + v[j].z*v[j].z + v[j].w*v[j].w;
    }
    #pragma unroll
    for (int o = 16; o; o >>= 1) ss += __shfl_xor_sync(0xffffffffu, ss, o);
    float sc = rsqrtf(ss*(1.f/1024.f) + EPSRMS);
    __half2* zr = (__half2*)(z + tok*1024);
    #pragma unroll
    for (int j = 0; j < 8; j++){
        int p = lane + 32*j;
        zr[2*p]     = __floats2half2_rn(v[j].x*sc, v[j].y*sc);
        zr[2*p + 1] = __floats2half2_rn(v[j].z*sc, v[j].w*sc);
    }
}

// ---------------- low-rank projection partials (K=256 per chunk, 4 slabs) ----------------
__global__ __launch_bounds__(256)
void p_k(const __half* __restrict__ z, const __half* __restrict__ B1,
         const __half* __restrict__ B2, int halves, int ldB){
    extern __shared__ float sm[];
    uint32_t sb = smem_u32(sm);
    int tid = threadIdx.x, warp = tid >> 5, lane = tid & 31;
    int wm = warp >> 1, wn = warp & 1;
    int tile = blockIdx.x, chunk = blockIdx.y;
    int batch = tile >> 4, seq0 = (tile & 15) << 7;
    const __half* zb = z + (size_t)batch*2048*1024;
    int half = (halves == 2) ? (chunk >> 2) : 0;
    int colbase = ((halves == 2) ? (chunk & 3) : chunk) << 8;
    int koff = half*1024 + colbase;

    float4 acc[8];
    #pragma unroll
    for (int i = 0; i < 8; i++) acc[i] = make_float4(0.f,0.f,0.f,0.f);

    auto fill = [&](int s, int buf){
        uint32_t aB = sb + (uint32_t)buf*24576u;
        uint32_t bB = aB + 16384u;
        stage_tok(aB, zb, seq0, half, colbase + (s << 6));
        int ko = koff + (s << 6);
        #pragma unroll
        for (int i = 0; i < 2; i++){
            int idx = tid + i*256;
            int r = idx >> 3, c4 = idx & 7;
            const __half* src = ((r < 32) ? B1 : B2) + (size_t)(r & 31)*ldB + ko + (c4 << 3);
            cp16(bB + r*128 + ((uint32_t)(c4 ^ (r & 7)) << 4), src, 16);
        }
    };

    fill(0, 0); CPCOMMIT();
    fill(1, 1); CPCOMMIT();
    for (int s = 0; s < 4; s++){
        CPWAITG1(); __syncthreads();
        uint32_t aB = sb + (uint32_t)(s % 3)*24576u;
        compLh<2,4>(aB, aB + 16384u, acc, wm*32, wn*32, lane);
        if (s + 2 < 4) fill(s + 2, (s + 2) % 3);
        CPCOMMIT();
    }

    size_t tok0 = (size_t)tile*128;
    float* dst = g_part + (size_t)chunk*1048576u;
    int lr = lane >> 2, lc2 = (lane & 3)*2;
    #pragma unroll
    for (int m = 0; m < 2; m++)
        #pragma unroll
        for (int n = 0; n < 4; n++){
            int r0 = wm*32 + m*16 + lr;
            int col = wn*32 + n*8 + lc2;
            float4 d = acc[m*4 + n];
            *(float2*)(dst + (tok0 + r0    )*64 + col) = make_float2(d.x, d.y);
            *(float2*)(dst + (tok0 + r0 + 8)*64 + col) = make_float2(d.z, d.w);
        }
}

// reduce partials -> fp16
__global__ void pred_k(__half* __restrict__ dst, const float* __restrict__ src,
                       int nch, size_t cstride, int n4){
    int i = blockIdx.x*256 + threadIdx.x;
    if (i >= n4) return;
    float4 a = ((const float4*)src)[i];
    for (int c = 1; c < nch; c++){
        float4 v = ((const float4*)(src + (size_t)c*cstride))[i];
        a.x += v.x; a.y += v.y; a.z += v.z; a.w += v.w;
    }
    __half2* d2 = (__half2*)dst;
    d2[2*i]     = __floats2half2_rn(a.x, a.y);
    d2[2*i + 1] = __floats2half2_rn(a.z, a.w);
}

// ---------------- iteration main GEMM (4 weight slabs + 1 shared lowrank slab) ----------
__global__ __launch_bounds__(256)
void main_k(const __half* __restrict__ z, const __half* __restrict__ P,
            const float* __restrict__ hin, float* __restrict__ hout,
            const __half* __restrict__ Wg, const __half* __restrict__ Wu,
            const __half* __restrict__ Ag, const __half* __restrict__ Au){
    extern __shared__ float sm[];
    uint32_t sb = smem_u32(sm);
    int tid = threadIdx.x, warp = tid >> 5, lane = tid & 31;
    int wm = warp >> 1, wn = warp & 1;
    int tile = blockIdx.x, nb2 = blockIdx.y;
    int nblk = nb2 >> 1, nh = nb2 & 1;
    int batch = tile >> 4, seq0 = (tile & 15) << 7;
    const __half* zb = z + (size_t)batch*2048*1024;
    int shift = (nblk >= 4) ? 1 : 0;
    int colbase0 = (nblk & 3) << 8;
    size_t tok0 = (size_t)tile*128;
    int wrow0 = nblk*128 + nh*64;

    float4 accg[8], accu[8];
    #pragma unroll
    for (int i = 0; i < 8; i++){
        accg[i] = make_float4(0.f,0.f,0.f,0.f);
        accu[i] = make_float4(0.f,0.f,0.f,0.f);
    }

    auto fill = [&](int s, int buf){
        uint32_t aB = sb + (uint32_t)buf*32768u;
        uint32_t gB = aB + 16384u, uB = aB + 24576u;
        if (s < 4){
            stage_tok(aB, zb, seq0, shift, colbase0 + (s << 6));
            const __half* g = Wg + (size_t)wrow0*256 + (s << 6);
            const __half* u = Wu + (size_t)wrow0*256 + (s << 6);
            #pragma unroll
            for (int i = 0; i < 2; i++){
                int idx = tid + i*256;
                int r = idx >> 3, c4 = idx & 7;
                uint32_t so = r*128 + ((uint32_t)(c4 ^ (r & 7)) << 4);
                cp16(gB + so, g + (size_t)r*256 + (c4 << 3), 16);
                cp16(uB + so, u + (size_t)r*256 + (c4 << 3), 16);
            }
        } else {
            // shared lowrank slab: A = P[:,0:64]; Bg = [Ag|0], Bu = [0|Au]
            stage_tile<1024>(aB, P + tok0*64, 64);
            #pragma unroll
            for (int i = 0; i < 2; i++){
                int idx = tid + i*256;
                int r = idx >> 3, c4 = idx & 7;
                uint32_t so = r*128 + ((uint32_t)(c4 ^ (r & 7)) << 4);
                int glo = (c4 < 4);
                cp16(gB + so, Ag + (size_t)(wrow0 + r)*32 + ((glo ? c4 : 0) << 3), glo ? 16 : 0);
                cp16(uB + so, Au + (size_t)(wrow0 + r)*32 + ((glo ? 0 : (c4 - 4)) << 3), glo ? 0 : 16);
            }
        }
    };

    fill(0, 0); CPCOMMIT();
    fill(1, 1); CPCOMMIT();
    for (int s = 0; s < 5; s++){
        CPWAITG1(); __syncthreads();
        uint32_t aB = sb + (uint32_t)(s % 3)*32768u;
        compL2h<2,4>(aB, aB + 16384u, aB + 24576u, accg, accu, wm*32, wn*32, lane);
        if (s + 2 < 5) fill(s + 2, (s + 2) % 3);
        CPCOMMIT();
    }

    int lr = lane >> 2, lc2 = (lane & 3)*2;
    #pragma unroll
    for (int m = 0; m < 2; m++)
        #pragma unroll
        for (int n = 0; n < 4; n++){
            int r0 = wm*32 + m*16 + lr;
            int col = wrow0 + wn*32 + n*8 + lc2;
            float4 dg = accg[m*4 + n], du = accu[m*4 + n];
            size_t ta = tok0 + r0, tb = ta + 8;
            float2 ha = *(const float2*)(hin + ta*1024 + col);
            float2 hb = *(const float2*)(hin + tb*1024 + col);
            float2 oa, ob;
            oa.x = fmaf(sigm(dg.x), du.x, ha.x);
            oa.y = fmaf(sigm(dg.y), du.y, ha.y);
            ob.x = fmaf(sigm(dg.z), du.z, hb.x);
            ob.y = fmaf(sigm(dg.w), du.w, hb.y);
            *(float2*)(hout + ta*1024 + col) = oa;
            *(float2*)(hout + tb*1024 + col) = ob;
        }
}

// ---------------- fused ff GEMM: g phase -> park, f phase -> silu(g)*f -> g_ff ------------
// 6 slabs: [z0, z1, lr_g, z0, z1, lr_f]; smem park of g accumulators between phases.
__global__ __launch_bounds__(256)
void ff_k(const __half* __restrict__ z, const __half* __restrict__ P,
          const __half* __restrict__ Wg, const __half* __restrict__ Wf,
          const __half* __restrict__ Ag, const __half* __restrict__ Af){
    extern __shared__ float sm[];
    uint32_t sb = smem_u32(sm);
    float* park = sm + 116736/4;
    int tid = threadIdx.x, warp = tid >> 5, lane = tid & 31;
    int wm = warp >> 1, wn = warp & 1;
    int tile = blockIdx.x, nblk = blockIdx.y, nsub = blockIdx.z;
    int n0 = nblk*352 + nsub*176;
    size_t tok0 = (size_t)tile*128;

    float4 acc[22];
    #pragma unroll
    for (int i = 0; i < 22; i++) acc[i] = make_float4(0.f,0.f,0.f,0.f);

    auto fill = [&](int q, int buf){
        uint32_t aB = sb + (uint32_t)buf*38912u;
        uint32_t bB = aB + 16384u;
        int ph = (q >= 3), s = ph ? (q - 3) : q;
        const __half* W = ph ? Wf : Wg;
        if (s < 2){
            stage_tile<1024>(aB, z + tok0*1024 + nblk*128 + (s << 6), 1024);
            stage_tile<1408>(bB, W + (size_t)n0*128 + (s << 6), 128);
        } else {
            stage_tile<1024>(aB, P + tok0*64, 64);
            const __half* Alr = ph ? Af : Ag;
            #pragma unroll
            for (int i = 0; i < 6; i++){
                int idx = tid + i*256;
                if (idx >= 1408) continue;
                int r = idx >> 3, c4 = idx & 7;
                uint32_t so = bB + r*128 + ((uint32_t)(c4 ^ (r & 7)) << 4);
                int lo = (c4 < 4);
                int use = ph ? !lo : lo;             // g: chunks 0-3; f: chunks 4-7
                int cc = ph ? (c4 - 4) : c4;
                cp16(so, Alr + (size_t)(n0 + r)*32 + ((use ? cc : 0) << 3), use ? 16 : 0);
            }
        }
    };

    fill(0, 0); CPCOMMIT();
    fill(1, 1); CPCOMMIT();
    for (int q = 0; q < 6; q++){
        CPWAITG1(); __syncthreads();
        uint32_t aB = sb + (uint32_t)(q % 3)*38912u;
        compLh<2,11>(aB, aB + 16384u, acc, wm*32, wn*88, lane);
        if (q == 2){
            // park g accumulators, reset for f phase
            float4* pk = (float4*)park + (size_t)tid*22;
            #pragma unroll
            for (int i = 0; i < 22; i++){
                pk[i] = acc[i];
                acc[i] = make_float4(0.f,0.f,0.f,0.f);
            }
        }
        if (q + 2 < 6) fill(q + 2, (q + 2) % 3);
        CPCOMMIT();
    }

    const float4* pk = (const float4*)park + (size_t)tid*22;
    int lr = lane >> 2, lc2 = (lane & 3)*2;
    #pragma unroll
    for (int m = 0; m < 2; m++)
        #pragma unroll
        for (int n = 0; n < 11; n++){
            int r0 = wm*32 + m*16 + lr;
            int col = n0 + wn*88 + n*8 + lc2;
            float4 f = acc[m*11 + n];
            float4 g = pk[m*11 + n];
            size_t ia = (tok0 + r0)*2816 + col;
            size_t ib = (tok0 + r0 + 8)*2816 + col;
            *(__half2*)(g_ff + ia) = __floats2half2_rn(g.x*sigm(g.x)*f.x, g.y*sigm(g.y)*f.y);
            *(__half2*)(g_ff + ib) = __floats2half2_rn(g.z*sigm(g.z)*f.z, g.w*sigm(g.w)*f.w);
        }
}

// ---------------- Pp partials: ff . ffp_B^T, K-split 8 x 352 (6 slabs, tail zfill) --------
__global__ __launch_bounds__(256)
void pp_k(const __half* __restrict__ ffpB){
    extern __shared__ float sm[];
    uint32_t sb = smem_u32(sm);
    int tid = threadIdx.x, warp = tid >> 5, lane = tid & 31;
    int wm = warp >> 1, wn = warp & 1;
    int tile = blockIdx.x, chunk = blockIdx.y;
    size_t tok0 = (size_t)tile*128;

    float4 acc[4];
    #pragma unroll
    for (int i = 0; i < 4; i++) acc[i] = make_float4(0.f,0.f,0.f,0.f);

    auto fill = [&](int s, int buf){
        uint32_t aB = sb + (uint32_t)buf*20480u;
        uint32_t bB = aB + 16384u;
        int vc = (s < 5) ? 8 : 4;                    // tail slab: 32 valid cols
        stage_tile_vc<1024>(aB, g_ff + tok0*2816 + chunk*352 + (s << 6), 2816, vc);
        stage_tile_vc<256>(bB, ffpB + chunk*352 + (s << 6), 2816, vc);
    };

    fill(0, 0); CPCOMMIT();
    fill(1, 1); CPCOMMIT();
    for (int s = 0; s < 6; s++){
        CPWAITG1(); __syncthreads();
        uint32_t aB = sb + (uint32_t)(s % 3)*20480u;
        compLh<2,2>(aB, aB + 16384u, acc, wm*32, wn*16, lane);
        if (s + 2 < 6) fill(s + 2, (s + 2) % 3);
        CPCOMMIT();
    }

    float* dst = g_part + (size_t)chunk*524288u;
    int lr = lane >> 2, lc2 = (lane & 3)*2;
    #pragma unroll
    for (int m = 0; m < 2; m++)
        #pragma unroll
        for (int n = 0; n < 2; n++){
            int r0 = wm*32 + m*16 + lr;
            int col = wn*16 + n*8 + lc2;
            float4 d = acc[m*2 + n];
            *(float2*)(dst + (tok0 + r0    )*32 + col) = make_float2(d.x, d.y);
            *(float2*)(dst + (tok0 + r0 + 8)*32 + col) = make_float2(d.z, d.w);
        }
}

// ---------------- out = h + ffp(ff) (5 full + tail + lowrank = 7 slabs) ----------------
__global__ __launch_bounds__(256)
void out_k(const float* __restrict__ hin, float* __restrict__ out,
           const __half* __restrict__ Wp, const __half* __restrict__ Ap){
    extern __shared__ float sm[];
    uint32_t sb = smem_u32(sm);
    int tid = threadIdx.x, warp = tid >> 5, lane = tid & 31;
    int wm = warp >> 1, wn = warp & 1;
    int tile = blockIdx.x, nb2 = blockIdx.y;
    int nblk = nb2 >> 1, nh = nb2 & 1;
    size_t tok0 = (size_t)tile*128;
    int wrow0 = nblk*128 + nh*64;

    float4 acc[8];
    #pragma unroll
    for (int i = 0; i < 8; i++) acc[i] = make_float4(0.f,0.f,0.f,0.f);

    auto fill = [&](int s, int buf){
        uint32_t aB = sb + (uint32_t)buf*24576u;
        uint32_t bB = aB + 16384u;
        if (s < 6){
            int vc = (s < 5) ? 8 : 4;
            stage_tile_vc<1024>(aB, g_ff + tok0*2816 + nblk*352 + (s << 6), 2816, vc);
            stage_tile_vc<512>(bB, Wp + (size_t)wrow0*352 + (s << 6), 352, vc);
        } else {
            stage_tile_vc<1024>(aB, g_Pp + tok0*32, 32, 4);
            stage_tile_vc<512>(bB, Ap + (size_t)wrow0*32, 32, 4);
        }
    };

    fill(0, 0); CPCOMMIT();
    fill(1, 1); CPCOMMIT();
    for (int s = 0; s < 7; s++){
        CPWAITG1(); __syncthreads();
        uint32_t aB = sb + (uint32_t)(s % 3)*24576u;
        compLh<2,4>(aB, aB + 16384u, acc, wm*32, wn*32, lane);
        if (s + 2 < 7) fill(s + 2, (s + 2) % 3);
        CPCOMMIT();
    }

    int lr = lane >> 2, lc2 = (lane & 3)*2;
    #pragma unroll
    for (int m = 0; m < 2; m++)
        #pragma unroll
        for (int n = 0; n < 4; n++){
            int r0 = wm*32 + m*16 + lr;
            int col = wrow0 + wn*32 + n*8 + lc2;
            float4 d = acc[m*4 + n];
            size_t ta = tok0 + r0, tb = ta + 8;
            float2 ha = *(const float2*)(hin + ta*1024 + col);
            float2 hb = *(const float2*)(hin + tb*1024 + col);
            *(float2*)(out + ta*1024 + col) = make_float2(ha.x + d.x, ha.y + d.y);
            *(float2*)(out + tb*1024 + col) = make_float2(hb.x + d.z, hb.y + d.w);
        }
}

// ---------------- launcher ----------------
template <typename T>
static void* symaddr(const T& s){
    void* p = nullptr;
    cudaGetSymbolAddress(&p, s);
    return p;
}

extern "C" void kernel_launch(void* const* d_in, const int* in_sizes, int n_in,
                              void* d_out, int out_size) {
    const float* x     = (const float*)d_in[0];
    const float* fg_W  = (const float*)d_in[1];
    const float* fg_A  = (const float*)d_in[2];
    const float* fg_B  = (const float*)d_in[3];
    const float* gu_W  = (const float*)d_in[4];
    const float* gu_A  = (const float*)d_in[5];
    const float* gu_B  = (const float*)d_in[6];
    const float* ffg_W = (const float*)d_in[7];
    const float* ffg_A = (const float*)d_in[8];
    const float* ffg_B = (const float*)d_in[9];
    const float* fff_W = (const float*)d_in[10];
    const float* fff_A = (const float*)d_in[11];
    const float* fff_B = (const float*)d_in[12];
    const float* ffp_W = (const float*)d_in[13];
    const float* ffp_A = (const float*)d_in[14];
    const float* ffp_B = (const float*)d_in[15];
    float* out = (float*)d_out;

    __half* z    = (__half*)symaddr(g_z);
    float*  h0   = (float*)symaddr(g_h0);
    float*  h1   = (float*)symaddr(g_h1);
    __half* P    = (__half*)symaddr(g_P);
    __half* Pp   = (__half*)symaddr(g_Pp);
    float*  part = (float*)symaddr(g_part);
    __half* wh   = (__half*)symaddr(g_wh);

    const int SM_P    = 3*24576;            // 72 KB
    const int SM_MAIN = 3*32768;            // 96 KB
    const int SM_FF   = 3*38912 + 90112;    // 202 KB (3-stage + park)
    const int SM_PP   = 3*20480;            // 60 KB
    const int SM_OUT  = 3*24576;            // 72 KB
    cudaFuncSetAttribute(p_k,    cudaFuncAttributeMaxDynamicSharedMemorySize, SM_P);
    cudaFuncSetAttribute(main_k, cudaFuncAttributeMaxDynamicSharedMemorySize, SM_MAIN);
    cudaFuncSetAttribute(ff_k,   cudaFuncAttributeMaxDynamicSharedMemorySize, SM_FF);
    cudaFuncSetAttribute(pp_k,   cudaFuncAttributeMaxDynamicSharedMemorySize, SM_PP);
    cudaFuncSetAttribute(out_k,  cudaFuncAttributeMaxDynamicSharedMemorySize, SM_OUT);

    cvt_k<<<dim3(352, 15), 256>>>(fg_W, gu_W, fg_A, gu_A, fg_B, gu_B,
                                  ffg_W, ffg_A, ffg_B, fff_W, fff_A, fff_B,
                                  ffp_W, ffp_A, ffp_B);

    const float* hcur = x;
    float* bufs[2] = {h0, h1};
    for (int it = 0; it < 4; it++){
        float* hnext = bufs[it & 1];
        rms_k<<<2048, 256>>>(hcur, z);
        p_k<<<dim3(128, 8), 256, SM_P>>>(z, wh + W_FGB, wh + W_GUB, 2, 2048);
        pred_k<<<1024, 256>>>(P, part, 8, (size_t)1048576, 262144);
        main_k<<<dim3(128, 16), 256, SM_MAIN>>>(z, P, hcur, hnext,
                                                wh + W_FGW, wh + W_GUW,
                                                wh + W_FGA, wh + W_GUA);
        hcur = hnext;
    }
    rms_k<<<2048, 256>>>(hcur, z);
    p_k<<<dim3(128, 4), 256, SM_P>>>(z, wh + W_FFGB, wh + W_FFFB, 1, 1024);
    pred_k<<<1024, 256>>>(P, part, 4, (size_t)1048576, 262144);
    ff_k<<<dim3(128, 8, 2), 256, SM_FF>>>(z, P, wh + W_FFGW, wh + W_FFFW,
                                          wh + W_FFGA, wh + W_FFFA);
    pp_k<<<dim3(128, 8), 256, SM_PP>>>(wh + W_FFPB);
    pred_k<<<512, 256>>>(Pp, part, 8, (size_t)524288, 131072);
    out_k<<<dim3(128, 16), 256, SM_OUT>>>(hcur, out, wh + W_FFPW, wh + W_FFPA);
}